// round 2
// baseline (speedup 1.0000x reference)
#include <cuda_runtime.h>
#include <cuda_bf16.h>

#define DM   1024
#define SEQ  2048
#define MTOK 4096   // BATCH*SEQ
#define NHEAD 16
#define HDIM 64

// Scratch (allocation-free rule: __device__ globals). Accessed directly from
// device code — no cudaGetSymbolAddress needed in kernel_launch.
__device__ float g_Q[(size_t)MTOK * DM];
__device__ float g_K[(size_t)MTOK * DM];
__device__ float g_V[(size_t)MTOK * DM];
__device__ float g_A[(size_t)MTOK * DM];

// ---------------------------------------------------------------------------
// GEMM: C[m,n] = sum_k A[m,k] * W[n,k]   (A: [M,1024] row-major, W: [1024,1024])
// BM=BN=128, BK=8, 256 threads, 8x8 microtile. Optional fused RoPE epilogue.
// SRC: 0 = external pointer, 1 = g_A.   DST: 0=g_Q 1=g_K 2=g_V 3=external.
// ---------------------------------------------------------------------------
template<bool ROPE, int SRC, int DST>
__global__ __launch_bounds__(256, 2)
void gemm_nt_kernel(const float* __restrict__ Aext, const float* __restrict__ W,
                    float* __restrict__ Cext, const int* __restrict__ tp)
{
    const float* A = (SRC == 0) ? Aext : g_A;
    float* C;
    if      (DST == 0) C = g_Q;
    else if (DST == 1) C = g_K;
    else if (DST == 2) C = g_V;
    else               C = Cext;

    __shared__ float As[8][128];
    __shared__ float Bs[8][128];

    const int tid = threadIdx.x;
    const int bm = blockIdx.y;
    const int bn = blockIdx.x;
    const int ty = tid >> 4;       // 0..15
    const int tx = tid & 15;       // 0..15

    const int lr = tid >> 1;        // 0..127  (load row)
    const int lc = (tid & 1) * 4;   // 0 or 4  (load col group)

    const float* Ag = A + (size_t)(bm * 128 + lr) * DM + lc;
    const float* Wg = W + (size_t)(bn * 128 + lr) * DM + lc;

    float acc[8][8];
    #pragma unroll
    for (int i = 0; i < 8; i++)
        #pragma unroll
        for (int j = 0; j < 8; j++)
            acc[i][j] = 0.0f;

    for (int k0 = 0; k0 < DM; k0 += 8) {
        float4 av = *(const float4*)(Ag + k0);
        float4 wv = *(const float4*)(Wg + k0);
        As[lc + 0][lr] = av.x; As[lc + 1][lr] = av.y;
        As[lc + 2][lr] = av.z; As[lc + 3][lr] = av.w;
        Bs[lc + 0][lr] = wv.x; Bs[lc + 1][lr] = wv.y;
        Bs[lc + 2][lr] = wv.z; Bs[lc + 3][lr] = wv.w;
        __syncthreads();

        #pragma unroll
        for (int k = 0; k < 8; k++) {
            float4 a0 = *(const float4*)&As[k][ty * 8];
            float4 a1 = *(const float4*)&As[k][ty * 8 + 4];
            float4 b0 = *(const float4*)&Bs[k][tx * 8];
            float4 b1 = *(const float4*)&Bs[k][tx * 8 + 4];
            float a[8] = {a0.x, a0.y, a0.z, a0.w, a1.x, a1.y, a1.z, a1.w};
            float b[8] = {b0.x, b0.y, b0.z, b0.w, b1.x, b1.y, b1.z, b1.w};
            #pragma unroll
            for (int i = 0; i < 8; i++)
                #pragma unroll
                for (int j = 0; j < 8; j++)
                    acc[i][j] = fmaf(a[i], b[j], acc[i][j]);
        }
        __syncthreads();
    }

    const int rowbase = bm * 128 + ty * 8;
    const int colbase = bn * 128 + tx * 8;

    #pragma unroll
    for (int i = 0; i < 8; i++) {
        const int r = rowbase + i;
        float* crow = C + (size_t)r * DM + colbase;
        if (ROPE) {
            const float pos = (float)tp[r & (SEQ - 1)];
            float outv[8];
            #pragma unroll
            for (int jj = 0; jj < 8; jj += 2) {
                const int d_even = (colbase + jj) & (HDIM - 1);  // even index in head
                // freq = theta^(-d_even/64) = exp(-d_even * ln(10000)/64)
                const float freq = expf(-(float)d_even * 0.14391156831212787f);
                const float ang = pos * freq;
                float s, c;
                sincosf(ang, &s, &c);
                const float e = acc[i][jj];
                const float o = acc[i][jj + 1];
                outv[jj]     = e * c - o * s;
                outv[jj + 1] = e * s + o * c;
            }
            *(float4*)(crow)     = make_float4(outv[0], outv[1], outv[2], outv[3]);
            *(float4*)(crow + 4) = make_float4(outv[4], outv[5], outv[6], outv[7]);
        } else {
            *(float4*)(crow)     = make_float4(acc[i][0], acc[i][1], acc[i][2], acc[i][3]);
            *(float4*)(crow + 4) = make_float4(acc[i][4], acc[i][5], acc[i][6], acc[i][7]);
        }
    }
}

// ---------------------------------------------------------------------------
// Flash attention, causal. One block = 64 query rows of one (b,h).
// 128 threads: 2 threads per query row, each owning 32 of the 64 head dims.
// Reads g_Q/g_K/g_V, writes g_A.
// ---------------------------------------------------------------------------
__global__ __launch_bounds__(128, 1)
void flash_attn_kernel()
{
    __shared__ float Ks[64][64];
    __shared__ float Vs[64][64];

    const int qt = blockIdx.x;     // query tile 0..31
    const int bh = blockIdx.y;     // 0..31
    const int b  = bh >> 4;
    const int h  = bh & 15;

    const int t    = threadIdx.x;
    const int row  = t >> 1;       // 0..63 local query row
    const int half = t & 1;        // which 32-dim half

    const int qrow = qt * 64 + row;            // sequence position of query
    const size_t tokbase = (size_t)(b * SEQ);

    const float* qp = g_Q + (tokbase + qrow) * DM + h * HDIM + half * 32;
    float q[32];
    #pragma unroll
    for (int i = 0; i < 32; i++) q[i] = qp[i];

    float acc[32];
    #pragma unroll
    for (int i = 0; i < 32; i++) acc[i] = 0.0f;
    float m = -1e30f;
    float l = 0.0f;

    for (int kt = 0; kt <= qt; ++kt) {
        // load K/V tiles: 64x64 floats each, 128 threads x 8 float4
        #pragma unroll
        for (int i = 0; i < 8; i++) {
            const int f  = t + i * 128;        // float4 index 0..1023
            const int r  = f >> 4;
            const int c4 = (f & 15) << 2;
            const size_t g = (tokbase + kt * 64 + r) * DM + h * HDIM + c4;
            *(float4*)&Ks[r][c4] = *(const float4*)(g_K + g);
            *(float4*)&Vs[r][c4] = *(const float4*)(g_V + g);
        }
        __syncthreads();

        float sc[64];
        const bool diag = (kt == qt);
        #pragma unroll
        for (int j = 0; j < 64; j++) {
            const float4* kr = (const float4*)&Ks[j][half * 32];
            float s = 0.0f;
            #pragma unroll
            for (int dd = 0; dd < 8; dd++) {
                float4 kv = kr[dd];
                s = fmaf(q[dd * 4 + 0], kv.x, s);
                s = fmaf(q[dd * 4 + 1], kv.y, s);
                s = fmaf(q[dd * 4 + 2], kv.z, s);
                s = fmaf(q[dd * 4 + 3], kv.w, s);
            }
            s += __shfl_xor_sync(0xffffffffu, s, 1);
            s *= 0.125f;                        // 1/sqrt(64)
            if (diag && (kt * 64 + j > qrow)) s = -1e30f;
            sc[j] = s;
        }

        float tmax = -1e30f;
        #pragma unroll
        for (int j = 0; j < 64; j++) tmax = fmaxf(tmax, sc[j]);
        const float mnew = fmaxf(m, tmax);
        const float corr = __expf(m - mnew);
        l *= corr;
        #pragma unroll
        for (int dd = 0; dd < 32; dd++) acc[dd] *= corr;

        #pragma unroll
        for (int j = 0; j < 64; j++) {
            const float p = __expf(sc[j] - mnew);
            l += p;
            const float4* vr = (const float4*)&Vs[j][half * 32];
            #pragma unroll
            for (int dd = 0; dd < 8; dd++) {
                float4 vv = vr[dd];
                acc[dd * 4 + 0] = fmaf(p, vv.x, acc[dd * 4 + 0]);
                acc[dd * 4 + 1] = fmaf(p, vv.y, acc[dd * 4 + 1]);
                acc[dd * 4 + 2] = fmaf(p, vv.z, acc[dd * 4 + 2]);
                acc[dd * 4 + 3] = fmaf(p, vv.w, acc[dd * 4 + 3]);
            }
        }
        m = mnew;
        __syncthreads();
    }

    const float inv = 1.0f / l;
    float* op = g_A + (tokbase + qrow) * DM + h * HDIM + half * 32;
    #pragma unroll
    for (int dd = 0; dd < 32; dd += 4) {
        *(float4*)(op + dd) = make_float4(acc[dd] * inv, acc[dd + 1] * inv,
                                          acc[dd + 2] * inv, acc[dd + 3] * inv);
    }
}

// ---------------------------------------------------------------------------
extern "C" void kernel_launch(void* const* d_in, const int* in_sizes, int n_in,
                              void* d_out, int out_size)
{
    (void)in_sizes; (void)n_in; (void)out_size;
    const float* x  = (const float*)d_in[0];
    const float* Wq = (const float*)d_in[1];
    const float* Wk = (const float*)d_in[2];
    const float* Wv = (const float*)d_in[3];
    const float* Wo = (const float*)d_in[4];
    // d_in[5] = causal mask (tril by construction; applied analytically)
    const int*   tp = (const int*)d_in[6];
    float* out = (float*)d_out;

    dim3 ggrid(DM / 128, MTOK / 128);   // (8, 32)
    gemm_nt_kernel<true,  0, 0><<<ggrid, 256>>>(x, Wq, nullptr, tp);   // -> g_Q (+RoPE)
    gemm_nt_kernel<true,  0, 1><<<ggrid, 256>>>(x, Wk, nullptr, tp);   // -> g_K (+RoPE)
    gemm_nt_kernel<false, 0, 2><<<ggrid, 256>>>(x, Wv, nullptr, tp);   // -> g_V

    dim3 fgrid(SEQ / 64, 2 * NHEAD);    // (32, 32)
    flash_attn_kernel<<<fgrid, 128>>>();                               // -> g_A

    gemm_nt_kernel<false, 1, 3><<<ggrid, 256>>>(nullptr, Wo, out, tp); // g_A -> out
}

// round 7
// speedup vs baseline: 1.1679x; 1.1679x over previous
#include <cuda_runtime.h>
#include <cuda_bf16.h>
#include <cstdint>

#define DM   1024
#define SEQ  2048
#define MTOK 4096   // BATCH*SEQ
#define NHEAD 16
#define HDIM 64

// Scratch (allocation-free rule: __device__ globals)
__device__ float g_Q[(size_t)MTOK * DM];
__device__ float g_K[(size_t)MTOK * DM];
__device__ float g_V[(size_t)MTOK * DM];
__device__ float g_A[(size_t)MTOK * DM];

// ---------------------------------------------------------------------------
// tf32 helpers
// ---------------------------------------------------------------------------
__device__ __forceinline__ uint32_t f2tf32(float x) {
    uint32_t u;
    asm("cvt.rna.tf32.f32 %0, %1;" : "=r"(u) : "f"(x));
    return u;
}

__device__ __forceinline__ void mma8(float* c, const uint32_t* a, const uint32_t* b) {
    asm volatile(
        "mma.sync.aligned.m16n8k8.row.col.f32.tf32.tf32.f32 "
        "{%0,%1,%2,%3}, {%4,%5,%6,%7}, {%8,%9}, {%0,%1,%2,%3};"
        : "+f"(c[0]), "+f"(c[1]), "+f"(c[2]), "+f"(c[3])
        : "r"(a[0]), "r"(a[1]), "r"(a[2]), "r"(a[3]), "r"(b[0]), "r"(b[1]));
}

// ---------------------------------------------------------------------------
// GEMM: C[m,n] = sum_k A[m,k] * W[n,k]  via 3-pass split tf32 tensor-core mma.
// BM=BN=128, BK=16. 128 threads = 4 warps (2x2), warp tile 64x64.
// SRC: 0 = external, 1 = g_A.  DST: 0=g_Q 1=g_K 2=g_V 3=external.
// ---------------------------------------------------------------------------
#define BK 16
#define LDS_STRIDE 20   // BK + 4 pad: frag banks (20r+t) all distinct

template<bool ROPE, int SRC, int DST>
__global__ __launch_bounds__(128, 2)
void gemm_tf32_kernel(const float* __restrict__ Aext, const float* __restrict__ W,
                      float* __restrict__ Cext, const int* __restrict__ tp)
{
    const float* A = (SRC == 0) ? Aext : g_A;
    float* C;
    if      (DST == 0) C = g_Q;
    else if (DST == 1) C = g_K;
    else if (DST == 2) C = g_V;
    else               C = Cext;

    __shared__ float Ah[128][LDS_STRIDE];
    __shared__ float Al[128][LDS_STRIDE];
    __shared__ float Bh[128][LDS_STRIDE];
    __shared__ float Bl[128][LDS_STRIDE];

    const int tid    = threadIdx.x;
    const int warp   = tid >> 5;
    const int lane   = tid & 31;
    const int group  = lane >> 2;   // 0..7
    const int tq     = lane & 3;    // 0..3
    const int warp_m = warp & 1;    // 0..1
    const int warp_n = warp >> 1;   // 0..1

    const int bm = blockIdx.y;
    const int bn = blockIdx.x;

    float c[4][8][4];
    #pragma unroll
    for (int mt = 0; mt < 4; mt++)
        #pragma unroll
        for (int nt = 0; nt < 8; nt++)
            #pragma unroll
            for (int r = 0; r < 4; r++)
                c[mt][nt][r] = 0.0f;

    // loader mapping: f = tid + i*128 ; row = f>>2, c4 = f&3  (4 float4 per tile)
    const int lrow = tid >> 2;
    const int lc4  = (tid & 3) * 4;

    for (int k0 = 0; k0 < DM; k0 += BK) {
        #pragma unroll
        for (int i = 0; i < 4; i++) {
            const int row = lrow + i * 32;
            float4 av = *(const float4*)(A + (size_t)(bm * 128 + row) * DM + k0 + lc4);
            float4 wv = *(const float4*)(W + (size_t)(bn * 128 + row) * DM + k0 + lc4);

            float ax[4] = {av.x, av.y, av.z, av.w};
            float wx[4] = {wv.x, wv.y, wv.z, wv.w};
            #pragma unroll
            for (int e = 0; e < 4; e++) {
                uint32_t hu = f2tf32(ax[e]);
                float hf = __uint_as_float(hu);
                Ah[row][lc4 + e] = hf;
                Al[row][lc4 + e] = __uint_as_float(f2tf32(ax[e] - hf));
                uint32_t hw = f2tf32(wx[e]);
                float hwf = __uint_as_float(hw);
                Bh[row][lc4 + e] = hwf;
                Bl[row][lc4 + e] = __uint_as_float(f2tf32(wx[e] - hwf));
            }
        }
        __syncthreads();

        #pragma unroll
        for (int ks = 0; ks < 2; ks++) {
            const int kk = ks * 8 + tq;
            uint32_t ah[4][4], al[4][4];
            #pragma unroll
            for (int mt = 0; mt < 4; mt++) {
                const int r = warp_m * 64 + mt * 16 + group;
                ah[mt][0] = __float_as_uint(Ah[r][kk]);
                ah[mt][1] = __float_as_uint(Ah[r + 8][kk]);
                ah[mt][2] = __float_as_uint(Ah[r][kk + 4]);
                ah[mt][3] = __float_as_uint(Ah[r + 8][kk + 4]);
                al[mt][0] = __float_as_uint(Al[r][kk]);
                al[mt][1] = __float_as_uint(Al[r + 8][kk]);
                al[mt][2] = __float_as_uint(Al[r][kk + 4]);
                al[mt][3] = __float_as_uint(Al[r + 8][kk + 4]);
            }
            #pragma unroll
            for (int nt = 0; nt < 8; nt++) {
                const int n = warp_n * 64 + nt * 8 + group;
                uint32_t bh[2], bl[2];
                bh[0] = __float_as_uint(Bh[n][kk]);
                bh[1] = __float_as_uint(Bh[n][kk + 4]);
                bl[0] = __float_as_uint(Bl[n][kk]);
                bl[1] = __float_as_uint(Bl[n][kk + 4]);
                #pragma unroll
                for (int mt = 0; mt < 4; mt++) {
                    mma8(c[mt][nt], ah[mt], bl);   // hi*lo
                    mma8(c[mt][nt], al[mt], bh);   // lo*hi
                    mma8(c[mt][nt], ah[mt], bh);   // hi*hi
                }
            }
        }
        __syncthreads();
    }

    // epilogue
    const int rowbase = bm * 128 + warp_m * 64 + group;
    const int colbase = bn * 128 + warp_n * 64;

    #pragma unroll
    for (int mt = 0; mt < 4; mt++) {
        #pragma unroll
        for (int half = 0; half < 2; half++) {
            const int r = rowbase + mt * 16 + half * 8;
            float* crow = C + (size_t)r * DM;
            float pos = 0.0f;
            if (ROPE) pos = (float)tp[r & (SEQ - 1)];
            #pragma unroll
            for (int nt = 0; nt < 8; nt++) {
                const int col = colbase + nt * 8 + 2 * tq;
                float e = c[mt][nt][half * 2 + 0];
                float o = c[mt][nt][half * 2 + 1];
                if (ROPE) {
                    const int d_even = col & (HDIM - 1);
                    const float freq = expf(-(float)d_even * 0.14391156831212787f);
                    float s, cc;
                    sincosf(pos * freq, &s, &cc);
                    const float ne = e * cc - o * s;
                    const float no = e * s + o * cc;
                    e = ne; o = no;
                }
                *(float2*)(crow + col) = make_float2(e, o);
            }
        }
    }
}

// ---------------------------------------------------------------------------
// Flash attention, causal (unchanged from R2 — proven correct).
// ---------------------------------------------------------------------------
__global__ __launch_bounds__(128, 1)
void flash_attn_kernel()
{
    __shared__ float Ks[64][64];
    __shared__ float Vs[64][64];

    const int qt = blockIdx.x;
    const int bh = blockIdx.y;
    const int b  = bh >> 4;
    const int h  = bh & 15;

    const int t    = threadIdx.x;
    const int row  = t >> 1;
    const int half = t & 1;

    const int qrow = qt * 64 + row;
    const size_t tokbase = (size_t)(b * SEQ);

    const float* qp = g_Q + (tokbase + qrow) * DM + h * HDIM + half * 32;
    float q[32];
    #pragma unroll
    for (int i = 0; i < 32; i++) q[i] = qp[i];

    float acc[32];
    #pragma unroll
    for (int i = 0; i < 32; i++) acc[i] = 0.0f;
    float m = -1e30f;
    float l = 0.0f;

    for (int kt = 0; kt <= qt; ++kt) {
        #pragma unroll
        for (int i = 0; i < 8; i++) {
            const int f  = t + i * 128;
            const int r  = f >> 4;
            const int c4 = (f & 15) << 2;
            const size_t g = (tokbase + kt * 64 + r) * DM + h * HDIM + c4;
            *(float4*)&Ks[r][c4] = *(const float4*)(g_K + g);
            *(float4*)&Vs[r][c4] = *(const float4*)(g_V + g);
        }
        __syncthreads();

        float sc[64];
        const bool diag = (kt == qt);
        #pragma unroll
        for (int j = 0; j < 64; j++) {
            const float4* kr = (const float4*)&Ks[j][half * 32];
            float s = 0.0f;
            #pragma unroll
            for (int dd = 0; dd < 8; dd++) {
                float4 kv = kr[dd];
                s = fmaf(q[dd * 4 + 0], kv.x, s);
                s = fmaf(q[dd * 4 + 1], kv.y, s);
                s = fmaf(q[dd * 4 + 2], kv.z, s);
                s = fmaf(q[dd * 4 + 3], kv.w, s);
            }
            s += __shfl_xor_sync(0xffffffffu, s, 1);
            s *= 0.125f;
            if (diag && (kt * 64 + j > qrow)) s = -1e30f;
            sc[j] = s;
        }

        float tmax = -1e30f;
        #pragma unroll
        for (int j = 0; j < 64; j++) tmax = fmaxf(tmax, sc[j]);
        const float mnew = fmaxf(m, tmax);
        const float corr = __expf(m - mnew);
        l *= corr;
        #pragma unroll
        for (int dd = 0; dd < 32; dd++) acc[dd] *= corr;

        #pragma unroll
        for (int j = 0; j < 64; j++) {
            const float p = __expf(sc[j] - mnew);
            l += p;
            const float4* vr = (const float4*)&Vs[j][half * 32];
            #pragma unroll
            for (int dd = 0; dd < 8; dd++) {
                float4 vv = vr[dd];
                acc[dd * 4 + 0] = fmaf(p, vv.x, acc[dd * 4 + 0]);
                acc[dd * 4 + 1] = fmaf(p, vv.y, acc[dd * 4 + 1]);
                acc[dd * 4 + 2] = fmaf(p, vv.z, acc[dd * 4 + 2]);
                acc[dd * 4 + 3] = fmaf(p, vv.w, acc[dd * 4 + 3]);
            }
        }
        m = mnew;
        __syncthreads();
    }

    const float inv = 1.0f / l;
    float* op = g_A + (tokbase + qrow) * DM + h * HDIM + half * 32;
    #pragma unroll
    for (int dd = 0; dd < 32; dd += 4) {
        *(float4*)(op + dd) = make_float4(acc[dd] * inv, acc[dd + 1] * inv,
                                          acc[dd + 2] * inv, acc[dd + 3] * inv);
    }
}

// ---------------------------------------------------------------------------
extern "C" void kernel_launch(void* const* d_in, const int* in_sizes, int n_in,
                              void* d_out, int out_size)
{
    (void)in_sizes; (void)n_in; (void)out_size;
    const float* x  = (const float*)d_in[0];
    const float* Wq = (const float*)d_in[1];
    const float* Wk = (const float*)d_in[2];
    const float* Wv = (const float*)d_in[3];
    const float* Wo = (const float*)d_in[4];
    const int*   tp = (const int*)d_in[6];
    float* out = (float*)d_out;

    dim3 ggrid(DM / 128, MTOK / 128);   // (8, 32)
    gemm_tf32_kernel<true,  0, 0><<<ggrid, 128>>>(x, Wq, nullptr, tp);
    gemm_tf32_kernel<true,  0, 1><<<ggrid, 128>>>(x, Wk, nullptr, tp);
    gemm_tf32_kernel<false, 0, 2><<<ggrid, 128>>>(x, Wv, nullptr, tp);

    dim3 fgrid(SEQ / 64, 2 * NHEAD);    // (32, 32)
    flash_attn_kernel<<<fgrid, 128>>>();

    gemm_tf32_kernel<false, 1, 3><<<ggrid, 128>>>(nullptr, Wo, out, tp);
}

// round 8
// speedup vs baseline: 2.0257x; 1.7345x over previous
#include <cuda_runtime.h>
#include <cuda_bf16.h>
#include <cstdint>

#define DM   1024
#define SEQ  2048
#define MTOK 4096   // BATCH*SEQ
#define NHEAD 16
#define HDIM 64

// Scratch (allocation-free rule: __device__ globals)
__device__ float g_Q[(size_t)MTOK * DM];
__device__ float g_K[(size_t)MTOK * DM];
__device__ float g_V[(size_t)MTOK * DM];
__device__ float g_A[(size_t)MTOK * DM];

// ---------------------------------------------------------------------------
// tf32 helpers
// ---------------------------------------------------------------------------
__device__ __forceinline__ uint32_t f2tf32(float x) {
    uint32_t u;
    asm("cvt.rna.tf32.f32 %0, %1;" : "=r"(u) : "f"(x));
    return u;
}

__device__ __forceinline__ void split2(float v, uint32_t& hi, uint32_t& lo) {
    uint32_t h = f2tf32(v);
    hi = h;
    lo = f2tf32(v - __uint_as_float(h));
}

__device__ __forceinline__ void mma8(float* c, const uint32_t* a, const uint32_t* b) {
    asm volatile(
        "mma.sync.aligned.m16n8k8.row.col.f32.tf32.tf32.f32 "
        "{%0,%1,%2,%3}, {%4,%5,%6,%7}, {%8,%9}, {%0,%1,%2,%3};"
        : "+f"(c[0]), "+f"(c[1]), "+f"(c[2]), "+f"(c[3])
        : "r"(a[0]), "r"(a[1]), "r"(a[2]), "r"(a[3]), "r"(b[0]), "r"(b[1]));
}

// ---------------------------------------------------------------------------
// GEMM: C[m,n] = sum_k A[m,k] * W[n,k]  via 3-pass split tf32 (unchanged, R7).
// ---------------------------------------------------------------------------
#define BK 16
#define LDS_STRIDE 20

template<bool ROPE, int SRC, int DST>
__global__ __launch_bounds__(128, 2)
void gemm_tf32_kernel(const float* __restrict__ Aext, const float* __restrict__ W,
                      float* __restrict__ Cext, const int* __restrict__ tp)
{
    const float* A = (SRC == 0) ? Aext : g_A;
    float* C;
    if      (DST == 0) C = g_Q;
    else if (DST == 1) C = g_K;
    else if (DST == 2) C = g_V;
    else               C = Cext;

    __shared__ float Ah[128][LDS_STRIDE];
    __shared__ float Al[128][LDS_STRIDE];
    __shared__ float Bh[128][LDS_STRIDE];
    __shared__ float Bl[128][LDS_STRIDE];

    const int tid    = threadIdx.x;
    const int warp   = tid >> 5;
    const int lane   = tid & 31;
    const int group  = lane >> 2;
    const int tq     = lane & 3;
    const int warp_m = warp & 1;
    const int warp_n = warp >> 1;

    const int bm = blockIdx.y;
    const int bn = blockIdx.x;

    float c[4][8][4];
    #pragma unroll
    for (int mt = 0; mt < 4; mt++)
        #pragma unroll
        for (int nt = 0; nt < 8; nt++)
            #pragma unroll
            for (int r = 0; r < 4; r++)
                c[mt][nt][r] = 0.0f;

    const int lrow = tid >> 2;
    const int lc4  = (tid & 3) * 4;

    for (int k0 = 0; k0 < DM; k0 += BK) {
        #pragma unroll
        for (int i = 0; i < 4; i++) {
            const int row = lrow + i * 32;
            float4 av = *(const float4*)(A + (size_t)(bm * 128 + row) * DM + k0 + lc4);
            float4 wv = *(const float4*)(W + (size_t)(bn * 128 + row) * DM + k0 + lc4);

            float ax[4] = {av.x, av.y, av.z, av.w};
            float wx[4] = {wv.x, wv.y, wv.z, wv.w};
            #pragma unroll
            for (int e = 0; e < 4; e++) {
                uint32_t hu = f2tf32(ax[e]);
                float hf = __uint_as_float(hu);
                Ah[row][lc4 + e] = hf;
                Al[row][lc4 + e] = __uint_as_float(f2tf32(ax[e] - hf));
                uint32_t hw = f2tf32(wx[e]);
                float hwf = __uint_as_float(hw);
                Bh[row][lc4 + e] = hwf;
                Bl[row][lc4 + e] = __uint_as_float(f2tf32(wx[e] - hwf));
            }
        }
        __syncthreads();

        #pragma unroll
        for (int ks = 0; ks < 2; ks++) {
            const int kk = ks * 8 + tq;
            uint32_t ah[4][4], al[4][4];
            #pragma unroll
            for (int mt = 0; mt < 4; mt++) {
                const int r = warp_m * 64 + mt * 16 + group;
                ah[mt][0] = __float_as_uint(Ah[r][kk]);
                ah[mt][1] = __float_as_uint(Ah[r + 8][kk]);
                ah[mt][2] = __float_as_uint(Ah[r][kk + 4]);
                ah[mt][3] = __float_as_uint(Ah[r + 8][kk + 4]);
                al[mt][0] = __float_as_uint(Al[r][kk]);
                al[mt][1] = __float_as_uint(Al[r + 8][kk]);
                al[mt][2] = __float_as_uint(Al[r][kk + 4]);
                al[mt][3] = __float_as_uint(Al[r + 8][kk + 4]);
            }
            #pragma unroll
            for (int nt = 0; nt < 8; nt++) {
                const int n = warp_n * 64 + nt * 8 + group;
                uint32_t bh[2], bl[2];
                bh[0] = __float_as_uint(Bh[n][kk]);
                bh[1] = __float_as_uint(Bh[n][kk + 4]);
                bl[0] = __float_as_uint(Bl[n][kk]);
                bl[1] = __float_as_uint(Bl[n][kk + 4]);
                #pragma unroll
                for (int mt = 0; mt < 4; mt++) {
                    mma8(c[mt][nt], ah[mt], bl);
                    mma8(c[mt][nt], al[mt], bh);
                    mma8(c[mt][nt], ah[mt], bh);
                }
            }
        }
        __syncthreads();
    }

    const int rowbase = bm * 128 + warp_m * 64 + group;
    const int colbase = bn * 128 + warp_n * 64;

    #pragma unroll
    for (int mt = 0; mt < 4; mt++) {
        #pragma unroll
        for (int half = 0; half < 2; half++) {
            const int r = rowbase + mt * 16 + half * 8;
            float* crow = C + (size_t)r * DM;
            float pos = 0.0f;
            if (ROPE) pos = (float)tp[r & (SEQ - 1)];
            #pragma unroll
            for (int nt = 0; nt < 8; nt++) {
                const int col = colbase + nt * 8 + 2 * tq;
                float e = c[mt][nt][half * 2 + 0];
                float o = c[mt][nt][half * 2 + 1];
                if (ROPE) {
                    const int d_even = col & (HDIM - 1);
                    const float freq = expf(-(float)d_even * 0.14391156831212787f);
                    float s, cc;
                    sincosf(pos * freq, &s, &cc);
                    const float ne = e * cc - o * s;
                    const float no = e * s + o * cc;
                    e = ne; o = no;
                }
                *(float2*)(crow + col) = make_float2(e, o);
            }
        }
    }
}

// ---------------------------------------------------------------------------
// Flash attention, causal, tensor-core (tf32 3-pass mma).
// Block = 64 query rows of one (b,h), 128 threads = 4 warps, warp = 16 rows.
// K tile in smem stride 68 (conflict-free for S B-frags),
// V tile in smem stride 72 (conflict-free for PV B-frags).
// ---------------------------------------------------------------------------
#define KS_STR 68
#define VS_STR 72

__global__ __launch_bounds__(128)
void flash_attn_mma_kernel()
{
    __shared__ float Ks[64 * KS_STR];
    __shared__ float Vs[64 * VS_STR];

    const int qt = blockIdx.x;     // query tile (64 rows)
    const int bh = blockIdx.y;
    const int b  = bh >> 4;
    const int h  = bh & 15;

    const int tid  = threadIdx.x;
    const int w    = tid >> 5;
    const int lane = tid & 31;
    const int g    = lane >> 2;    // 0..7
    const int tq   = lane & 3;     // 0..3

    const int r0 = qt * 64 + w * 16 + g;   // global seq row for c-elems 0,1
    const int r1 = r0 + 8;                 // for c-elems 2,3
    const size_t tok = (size_t)b * SEQ;

    // Q fragments, pre-scaled by 1/sqrt(64), hi/lo split, resident all block.
    uint32_t qh[8][4], ql[8][4];
    #pragma unroll
    for (int ks = 0; ks < 8; ks++) {
        const int c0 = h * HDIM + ks * 8 + tq;
        split2(0.125f * g_Q[(tok + r0) * DM + c0],     qh[ks][0], ql[ks][0]);
        split2(0.125f * g_Q[(tok + r1) * DM + c0],     qh[ks][1], ql[ks][1]);
        split2(0.125f * g_Q[(tok + r0) * DM + c0 + 4], qh[ks][2], ql[ks][2]);
        split2(0.125f * g_Q[(tok + r1) * DM + c0 + 4], qh[ks][3], ql[ks][3]);
    }

    float o[8][4];
    #pragma unroll
    for (int nt = 0; nt < 8; nt++)
        #pragma unroll
        for (int e = 0; e < 4; e++) o[nt][e] = 0.0f;

    float m0 = -1e30f, m1 = -1e30f;
    float l0 = 0.0f,   l1 = 0.0f;

    for (int kt = 0; kt <= qt; ++kt) {
        // ---- load K,V tiles (64x64 fp32 each) ----
        #pragma unroll
        for (int i = 0; i < 8; i++) {
            const int f  = tid + i * 128;
            const int r  = f >> 4;
            const int c4 = (f & 15) << 2;
            const size_t gidx = (tok + kt * 64 + r) * DM + h * HDIM + c4;
            *(float4*)&Ks[r * KS_STR + c4] = *(const float4*)(g_K + gidx);
            *(float4*)&Vs[r * VS_STR + c4] = *(const float4*)(g_V + gidx);
        }
        __syncthreads();

        // ---- S = Q K^T (scaled), 3-pass tf32 ----
        float s[8][4];
        #pragma unroll
        for (int nt = 0; nt < 8; nt++)
            #pragma unroll
            for (int e = 0; e < 4; e++) s[nt][e] = 0.0f;

        #pragma unroll
        for (int ks = 0; ks < 8; ks++) {
            #pragma unroll
            for (int nt = 0; nt < 8; nt++) {
                const float k0 = Ks[(nt * 8 + g) * KS_STR + ks * 8 + tq];
                const float k1 = Ks[(nt * 8 + g) * KS_STR + ks * 8 + tq + 4];
                uint32_t bhk[2], blk[2];
                split2(k0, bhk[0], blk[0]);
                split2(k1, bhk[1], blk[1]);
                mma8(s[nt], qh[ks], blk);
                mma8(s[nt], ql[ks], bhk);
                mma8(s[nt], qh[ks], bhk);
            }
        }

        // ---- causal mask on diagonal tile ----
        if (kt == qt) {
            #pragma unroll
            for (int nt = 0; nt < 8; nt++) {
                const int c = kt * 64 + nt * 8 + 2 * tq;
                if (c     > r0) s[nt][0] = -1e30f;
                if (c + 1 > r0) s[nt][1] = -1e30f;
                if (c     > r1) s[nt][2] = -1e30f;
                if (c + 1 > r1) s[nt][3] = -1e30f;
            }
        }

        // ---- online softmax (row stats via quad shuffles) ----
        float mx0 = -1e30f, mx1 = -1e30f;
        #pragma unroll
        for (int nt = 0; nt < 8; nt++) {
            mx0 = fmaxf(mx0, fmaxf(s[nt][0], s[nt][1]));
            mx1 = fmaxf(mx1, fmaxf(s[nt][2], s[nt][3]));
        }
        mx0 = fmaxf(mx0, __shfl_xor_sync(0xffffffffu, mx0, 1));
        mx0 = fmaxf(mx0, __shfl_xor_sync(0xffffffffu, mx0, 2));
        mx1 = fmaxf(mx1, __shfl_xor_sync(0xffffffffu, mx1, 1));
        mx1 = fmaxf(mx1, __shfl_xor_sync(0xffffffffu, mx1, 2));

        const float m0n = fmaxf(m0, mx0);
        const float m1n = fmaxf(m1, mx1);
        const float corr0 = __expf(m0 - m0n);
        const float corr1 = __expf(m1 - m1n);

        float sum0 = 0.0f, sum1 = 0.0f;
        #pragma unroll
        for (int nt = 0; nt < 8; nt++) {
            s[nt][0] = __expf(s[nt][0] - m0n); sum0 += s[nt][0];
            s[nt][1] = __expf(s[nt][1] - m0n); sum0 += s[nt][1];
            s[nt][2] = __expf(s[nt][2] - m1n); sum1 += s[nt][2];
            s[nt][3] = __expf(s[nt][3] - m1n); sum1 += s[nt][3];
        }
        sum0 += __shfl_xor_sync(0xffffffffu, sum0, 1);
        sum0 += __shfl_xor_sync(0xffffffffu, sum0, 2);
        sum1 += __shfl_xor_sync(0xffffffffu, sum1, 1);
        sum1 += __shfl_xor_sync(0xffffffffu, sum1, 2);
        l0 = l0 * corr0 + sum0;
        l1 = l1 * corr1 + sum1;
        m0 = m0n; m1 = m1n;

        #pragma unroll
        for (int nt = 0; nt < 8; nt++) {
            o[nt][0] *= corr0; o[nt][1] *= corr0;
            o[nt][2] *= corr1; o[nt][3] *= corr1;
        }

        // ---- O += P V, 3-pass tf32. Permute P from C-layout to A-layout. ----
        const int srcA = (lane & 28) | (tq >> 1);
        const int srcB = srcA | 2;
        const bool odd = (tq & 1);

        #pragma unroll
        for (int ks = 0; ks < 8; ks++) {
            const float pe  = __shfl_sync(0xffffffffu, s[ks][0], srcA);
            const float po  = __shfl_sync(0xffffffffu, s[ks][1], srcA);
            const float pe2 = __shfl_sync(0xffffffffu, s[ks][0], srcB);
            const float po2 = __shfl_sync(0xffffffffu, s[ks][1], srcB);
            const float re  = __shfl_sync(0xffffffffu, s[ks][2], srcA);
            const float ro  = __shfl_sync(0xffffffffu, s[ks][3], srcA);
            const float re2 = __shfl_sync(0xffffffffu, s[ks][2], srcB);
            const float ro2 = __shfl_sync(0xffffffffu, s[ks][3], srcB);

            uint32_t ph[4], pl[4];
            split2(odd ? po  : pe,  ph[0], pl[0]);   // P[g   ][8ks+tq]
            split2(odd ? ro  : re,  ph[1], pl[1]);   // P[g+8 ][8ks+tq]
            split2(odd ? po2 : pe2, ph[2], pl[2]);   // P[g   ][8ks+tq+4]
            split2(odd ? ro2 : re2, ph[3], pl[3]);   // P[g+8 ][8ks+tq+4]

            #pragma unroll
            for (int nt = 0; nt < 8; nt++) {
                const float v0 = Vs[(ks * 8 + tq)     * VS_STR + nt * 8 + g];
                const float v1 = Vs[(ks * 8 + tq + 4) * VS_STR + nt * 8 + g];
                uint32_t vh[2], vl[2];
                split2(v0, vh[0], vl[0]);
                split2(v1, vh[1], vl[1]);
                mma8(o[nt], ph, vl);
                mma8(o[nt], pl, vh);
                mma8(o[nt], ph, vh);
            }
        }
        __syncthreads();
    }

    // ---- normalize and store ----
    const float inv0 = 1.0f / l0;
    const float inv1 = 1.0f / l1;
    #pragma unroll
    for (int nt = 0; nt < 8; nt++) {
        const int col = h * HDIM + nt * 8 + 2 * tq;
        *(float2*)(g_A + (tok + r0) * DM + col) = make_float2(o[nt][0] * inv0, o[nt][1] * inv0);
        *(float2*)(g_A + (tok + r1) * DM + col) = make_float2(o[nt][2] * inv1, o[nt][3] * inv1);
    }
}

// ---------------------------------------------------------------------------
extern "C" void kernel_launch(void* const* d_in, const int* in_sizes, int n_in,
                              void* d_out, int out_size)
{
    (void)in_sizes; (void)n_in; (void)out_size;
    const float* x  = (const float*)d_in[0];
    const float* Wq = (const float*)d_in[1];
    const float* Wk = (const float*)d_in[2];
    const float* Wv = (const float*)d_in[3];
    const float* Wo = (const float*)d_in[4];
    const int*   tp = (const int*)d_in[6];
    float* out = (float*)d_out;

    dim3 ggrid(DM / 128, MTOK / 128);   // (8, 32)
    gemm_tf32_kernel<true,  0, 0><<<ggrid, 128>>>(x, Wq, nullptr, tp);
    gemm_tf32_kernel<true,  0, 1><<<ggrid, 128>>>(x, Wk, nullptr, tp);
    gemm_tf32_kernel<false, 0, 2><<<ggrid, 128>>>(x, Wv, nullptr, tp);

    dim3 fgrid(SEQ / 64, 2 * NHEAD);    // (32, 32)
    flash_attn_mma_kernel<<<fgrid, 128>>>();

    gemm_tf32_kernel<false, 1, 3><<<ggrid, 128>>>(nullptr, Wo, out, tp);
}

// round 9
// speedup vs baseline: 2.1476x; 1.0602x over previous
#include <cuda_runtime.h>
#include <cuda_bf16.h>
#include <cstdint>

#define DM   1024
#define SEQ  2048
#define MTOK 4096   // BATCH*SEQ
#define NHEAD 16
#define HDIM 64

// Scratch (allocation-free rule: __device__ globals)
__device__ float g_Q[(size_t)MTOK * DM];
__device__ float g_K[(size_t)MTOK * DM];
__device__ float g_V[(size_t)MTOK * DM];
__device__ float g_A[(size_t)MTOK * DM];

// ---------------------------------------------------------------------------
// tf32 helpers
// ---------------------------------------------------------------------------
__device__ __forceinline__ uint32_t f2tf32(float x) {
    uint32_t u;
    asm("cvt.rna.tf32.f32 %0, %1;" : "=r"(u) : "f"(x));
    return u;
}

__device__ __forceinline__ void split2(float v, uint32_t& hi, uint32_t& lo) {
    uint32_t h = f2tf32(v);
    hi = h;
    lo = f2tf32(v - __uint_as_float(h));
}

__device__ __forceinline__ void split4(float4 v, float4& hi, float4& lo) {
    uint32_t h, l;
    split2(v.x, h, l); hi.x = __uint_as_float(h); lo.x = __uint_as_float(l);
    split2(v.y, h, l); hi.y = __uint_as_float(h); lo.y = __uint_as_float(l);
    split2(v.z, h, l); hi.z = __uint_as_float(h); lo.z = __uint_as_float(l);
    split2(v.w, h, l); hi.w = __uint_as_float(h); lo.w = __uint_as_float(l);
}

__device__ __forceinline__ void mma8(float* c, const uint32_t* a, const uint32_t* b) {
    asm volatile(
        "mma.sync.aligned.m16n8k8.row.col.f32.tf32.tf32.f32 "
        "{%0,%1,%2,%3}, {%4,%5,%6,%7}, {%8,%9}, {%0,%1,%2,%3};"
        : "+f"(c[0]), "+f"(c[1]), "+f"(c[2]), "+f"(c[3])
        : "r"(a[0]), "r"(a[1]), "r"(a[2]), "r"(a[3]), "r"(b[0]), "r"(b[1]));
}

// ---------------------------------------------------------------------------
// GEMM: C[m,n] = sum_k A[m,k] * W[n,k]  via 3-pass split tf32 (unchanged, R7).
// ---------------------------------------------------------------------------
#define BK 16
#define LDS_STRIDE 20

template<bool ROPE, int SRC, int DST>
__global__ __launch_bounds__(128, 2)
void gemm_tf32_kernel(const float* __restrict__ Aext, const float* __restrict__ W,
                      float* __restrict__ Cext, const int* __restrict__ tp)
{
    const float* A = (SRC == 0) ? Aext : g_A;
    float* C;
    if      (DST == 0) C = g_Q;
    else if (DST == 1) C = g_K;
    else if (DST == 2) C = g_V;
    else               C = Cext;

    __shared__ float Ah[128][LDS_STRIDE];
    __shared__ float Al[128][LDS_STRIDE];
    __shared__ float Bh[128][LDS_STRIDE];
    __shared__ float Bl[128][LDS_STRIDE];

    const int tid    = threadIdx.x;
    const int warp   = tid >> 5;
    const int lane   = tid & 31;
    const int group  = lane >> 2;
    const int tq     = lane & 3;
    const int warp_m = warp & 1;
    const int warp_n = warp >> 1;

    const int bm = blockIdx.y;
    const int bn = blockIdx.x;

    float c[4][8][4];
    #pragma unroll
    for (int mt = 0; mt < 4; mt++)
        #pragma unroll
        for (int nt = 0; nt < 8; nt++)
            #pragma unroll
            for (int r = 0; r < 4; r++)
                c[mt][nt][r] = 0.0f;

    const int lrow = tid >> 2;
    const int lc4  = (tid & 3) * 4;

    for (int k0 = 0; k0 < DM; k0 += BK) {
        #pragma unroll
        for (int i = 0; i < 4; i++) {
            const int row = lrow + i * 32;
            float4 av = *(const float4*)(A + (size_t)(bm * 128 + row) * DM + k0 + lc4);
            float4 wv = *(const float4*)(W + (size_t)(bn * 128 + row) * DM + k0 + lc4);

            float ax[4] = {av.x, av.y, av.z, av.w};
            float wx[4] = {wv.x, wv.y, wv.z, wv.w};
            #pragma unroll
            for (int e = 0; e < 4; e++) {
                uint32_t hu = f2tf32(ax[e]);
                float hf = __uint_as_float(hu);
                Ah[row][lc4 + e] = hf;
                Al[row][lc4 + e] = __uint_as_float(f2tf32(ax[e] - hf));
                uint32_t hw = f2tf32(wx[e]);
                float hwf = __uint_as_float(hw);
                Bh[row][lc4 + e] = hwf;
                Bl[row][lc4 + e] = __uint_as_float(f2tf32(wx[e] - hwf));
            }
        }
        __syncthreads();

        #pragma unroll
        for (int ks = 0; ks < 2; ks++) {
            const int kk = ks * 8 + tq;
            uint32_t ah[4][4], al[4][4];
            #pragma unroll
            for (int mt = 0; mt < 4; mt++) {
                const int r = warp_m * 64 + mt * 16 + group;
                ah[mt][0] = __float_as_uint(Ah[r][kk]);
                ah[mt][1] = __float_as_uint(Ah[r + 8][kk]);
                ah[mt][2] = __float_as_uint(Ah[r][kk + 4]);
                ah[mt][3] = __float_as_uint(Ah[r + 8][kk + 4]);
                al[mt][0] = __float_as_uint(Al[r][kk]);
                al[mt][1] = __float_as_uint(Al[r + 8][kk]);
                al[mt][2] = __float_as_uint(Al[r][kk + 4]);
                al[mt][3] = __float_as_uint(Al[r + 8][kk + 4]);
            }
            #pragma unroll
            for (int nt = 0; nt < 8; nt++) {
                const int n = warp_n * 64 + nt * 8 + group;
                uint32_t bh[2], bl[2];
                bh[0] = __float_as_uint(Bh[n][kk]);
                bh[1] = __float_as_uint(Bh[n][kk + 4]);
                bl[0] = __float_as_uint(Bl[n][kk]);
                bl[1] = __float_as_uint(Bl[n][kk + 4]);
                #pragma unroll
                for (int mt = 0; mt < 4; mt++) {
                    mma8(c[mt][nt], ah[mt], bl);
                    mma8(c[mt][nt], al[mt], bh);
                    mma8(c[mt][nt], ah[mt], bh);
                }
            }
        }
        __syncthreads();
    }

    const int rowbase = bm * 128 + warp_m * 64 + group;
    const int colbase = bn * 128 + warp_n * 64;

    #pragma unroll
    for (int mt = 0; mt < 4; mt++) {
        #pragma unroll
        for (int half = 0; half < 2; half++) {
            const int r = rowbase + mt * 16 + half * 8;
            float* crow = C + (size_t)r * DM;
            float pos = 0.0f;
            if (ROPE) pos = (float)tp[r & (SEQ - 1)];
            #pragma unroll
            for (int nt = 0; nt < 8; nt++) {
                const int col = colbase + nt * 8 + 2 * tq;
                float e = c[mt][nt][half * 2 + 0];
                float o = c[mt][nt][half * 2 + 1];
                if (ROPE) {
                    const int d_even = col & (HDIM - 1);
                    const float freq = expf(-(float)d_even * 0.14391156831212787f);
                    float s, cc;
                    sincosf(pos * freq, &s, &cc);
                    const float ne = e * cc - o * s;
                    const float no = e * s + o * cc;
                    e = ne; o = no;
                }
                *(float2*)(crow + col) = make_float2(e, o);
            }
        }
    }
}

// ---------------------------------------------------------------------------
// Flash attention, causal, tensor-core tf32 3-pass with PRE-SPLIT smem tiles.
// Block = 128 query rows of one (b,h); 256 threads = 8 warps x 16 rows.
// Khi/Klo stride 68 (banks 4g+tq, conflict-free), Vhi/Vlo stride 72 (8tq+g).
// Dynamic smem: 2*64*68 + 2*64*72 floats = 71680 B.
// ---------------------------------------------------------------------------
#define KS_STR 68
#define VS_STR 72
#define FLASH_SMEM ((2 * 64 * KS_STR + 2 * 64 * VS_STR) * 4)

__global__ __launch_bounds__(256)
void flash_attn_mma_kernel()
{
    extern __shared__ float dsm[];
    float* Khi = dsm;
    float* Klo = Khi + 64 * KS_STR;
    float* Vhi = Klo + 64 * KS_STR;
    float* Vlo = Vhi + 64 * VS_STR;

    const int qt = blockIdx.x;     // 128-row query tile, 0..15
    const int bh = blockIdx.y;
    const int b  = bh >> 4;
    const int h  = bh & 15;

    const int tid  = threadIdx.x;
    const int w    = tid >> 5;     // 0..7
    const int lane = tid & 31;
    const int g    = lane >> 2;
    const int tq   = lane & 3;

    const int qbase = qt * 128;
    const int wlow  = qbase + w * 16;      // first row of this warp
    const int wmax  = wlow + 15;           // last row of this warp
    const int r0 = wlow + g;
    const int r1 = r0 + 8;
    const size_t tok = (size_t)b * SEQ;

    // Q fragments, pre-scaled by 1/sqrt(64), hi/lo split, resident all block.
    uint32_t qh[8][4], ql[8][4];
    #pragma unroll
    for (int ks = 0; ks < 8; ks++) {
        const int c0 = h * HDIM + ks * 8 + tq;
        split2(0.125f * g_Q[(tok + r0) * DM + c0],     qh[ks][0], ql[ks][0]);
        split2(0.125f * g_Q[(tok + r1) * DM + c0],     qh[ks][1], ql[ks][1]);
        split2(0.125f * g_Q[(tok + r0) * DM + c0 + 4], qh[ks][2], ql[ks][2]);
        split2(0.125f * g_Q[(tok + r1) * DM + c0 + 4], qh[ks][3], ql[ks][3]);
    }

    float o[8][4];
    #pragma unroll
    for (int nt = 0; nt < 8; nt++)
        #pragma unroll
        for (int e = 0; e < 4; e++) o[nt][e] = 0.0f;

    float m0 = -1e30f, m1 = -1e30f;
    float l0 = 0.0f,   l1 = 0.0f;

    const int ktmax = (qbase + 127) >> 6;   // 2*qt + 1

    for (int kt = 0; kt <= ktmax; ++kt) {
        // ---- cooperative load + tf32 pre-split of K,V tiles ----
        #pragma unroll
        for (int i = 0; i < 4; i++) {
            const int f  = tid + i * 256;       // float4 index 0..1023
            const int r  = f >> 4;
            const int c4 = (f & 15) << 2;
            const size_t gidx = (tok + kt * 64 + r) * DM + h * HDIM + c4;
            float4 kv = *(const float4*)(g_K + gidx);
            float4 vv = *(const float4*)(g_V + gidx);
            float4 khi, klo, vhi, vlo;
            split4(kv, khi, klo);
            split4(vv, vhi, vlo);
            *(float4*)&Khi[r * KS_STR + c4] = khi;
            *(float4*)&Klo[r * KS_STR + c4] = klo;
            *(float4*)&Vhi[r * VS_STR + c4] = vhi;
            *(float4*)&Vlo[r * VS_STR + c4] = vlo;
        }
        __syncthreads();

        if (kt * 64 <= wmax) {   // uniform per warp: skip fully-masked tiles
            // ---- S = Q K^T (scaled), 3-pass tf32 ----
            float s[8][4];
            #pragma unroll
            for (int nt = 0; nt < 8; nt++)
                #pragma unroll
                for (int e = 0; e < 4; e++) s[nt][e] = 0.0f;

            #pragma unroll
            for (int ks = 0; ks < 8; ks++) {
                #pragma unroll
                for (int nt = 0; nt < 8; nt++) {
                    const int base = (nt * 8 + g) * KS_STR + ks * 8 + tq;
                    uint32_t bhk[2], blk[2];
                    bhk[0] = __float_as_uint(Khi[base]);
                    bhk[1] = __float_as_uint(Khi[base + 4]);
                    blk[0] = __float_as_uint(Klo[base]);
                    blk[1] = __float_as_uint(Klo[base + 4]);
                    mma8(s[nt], qh[ks], blk);
                    mma8(s[nt], ql[ks], bhk);
                    mma8(s[nt], qh[ks], bhk);
                }
            }

            // ---- causal mask (only tiles touching the diagonal) ----
            if (kt * 64 + 63 > wlow) {
                #pragma unroll
                for (int nt = 0; nt < 8; nt++) {
                    const int c = kt * 64 + nt * 8 + 2 * tq;
                    if (c     > r0) s[nt][0] = -1e30f;
                    if (c + 1 > r0) s[nt][1] = -1e30f;
                    if (c     > r1) s[nt][2] = -1e30f;
                    if (c + 1 > r1) s[nt][3] = -1e30f;
                }
            }

            // ---- online softmax (row stats via quad shuffles) ----
            float mx0 = -1e30f, mx1 = -1e30f;
            #pragma unroll
            for (int nt = 0; nt < 8; nt++) {
                mx0 = fmaxf(mx0, fmaxf(s[nt][0], s[nt][1]));
                mx1 = fmaxf(mx1, fmaxf(s[nt][2], s[nt][3]));
            }
            mx0 = fmaxf(mx0, __shfl_xor_sync(0xffffffffu, mx0, 1));
            mx0 = fmaxf(mx0, __shfl_xor_sync(0xffffffffu, mx0, 2));
            mx1 = fmaxf(mx1, __shfl_xor_sync(0xffffffffu, mx1, 1));
            mx1 = fmaxf(mx1, __shfl_xor_sync(0xffffffffu, mx1, 2));

            const float m0n = fmaxf(m0, mx0);
            const float m1n = fmaxf(m1, mx1);
            const float corr0 = __expf(m0 - m0n);
            const float corr1 = __expf(m1 - m1n);

            float sum0 = 0.0f, sum1 = 0.0f;
            #pragma unroll
            for (int nt = 0; nt < 8; nt++) {
                s[nt][0] = __expf(s[nt][0] - m0n); sum0 += s[nt][0];
                s[nt][1] = __expf(s[nt][1] - m0n); sum0 += s[nt][1];
                s[nt][2] = __expf(s[nt][2] - m1n); sum1 += s[nt][2];
                s[nt][3] = __expf(s[nt][3] - m1n); sum1 += s[nt][3];
            }
            sum0 += __shfl_xor_sync(0xffffffffu, sum0, 1);
            sum0 += __shfl_xor_sync(0xffffffffu, sum0, 2);
            sum1 += __shfl_xor_sync(0xffffffffu, sum1, 1);
            sum1 += __shfl_xor_sync(0xffffffffu, sum1, 2);
            l0 = l0 * corr0 + sum0;
            l1 = l1 * corr1 + sum1;
            m0 = m0n; m1 = m1n;

            #pragma unroll
            for (int nt = 0; nt < 8; nt++) {
                o[nt][0] *= corr0; o[nt][1] *= corr0;
                o[nt][2] *= corr1; o[nt][3] *= corr1;
            }

            // ---- O += P V, 3-pass tf32; permute P C-layout -> A-layout ----
            const int srcA = (lane & 28) | (tq >> 1);
            const int srcB = srcA | 2;
            const bool odd = (tq & 1);

            #pragma unroll
            for (int ks = 0; ks < 8; ks++) {
                const float pe  = __shfl_sync(0xffffffffu, s[ks][0], srcA);
                const float po  = __shfl_sync(0xffffffffu, s[ks][1], srcA);
                const float pe2 = __shfl_sync(0xffffffffu, s[ks][0], srcB);
                const float po2 = __shfl_sync(0xffffffffu, s[ks][1], srcB);
                const float re  = __shfl_sync(0xffffffffu, s[ks][2], srcA);
                const float ro  = __shfl_sync(0xffffffffu, s[ks][3], srcA);
                const float re2 = __shfl_sync(0xffffffffu, s[ks][2], srcB);
                const float ro2 = __shfl_sync(0xffffffffu, s[ks][3], srcB);

                uint32_t ph[4], pl[4];
                split2(odd ? po  : pe,  ph[0], pl[0]);
                split2(odd ? ro  : re,  ph[1], pl[1]);
                split2(odd ? po2 : pe2, ph[2], pl[2]);
                split2(odd ? ro2 : re2, ph[3], pl[3]);

                #pragma unroll
                for (int nt = 0; nt < 8; nt++) {
                    const int base = (ks * 8 + tq) * VS_STR + nt * 8 + g;
                    uint32_t vh[2], vl[2];
                    vh[0] = __float_as_uint(Vhi[base]);
                    vh[1] = __float_as_uint(Vhi[base + 4 * VS_STR]);
                    vl[0] = __float_as_uint(Vlo[base]);
                    vl[1] = __float_as_uint(Vlo[base + 4 * VS_STR]);
                    mma8(o[nt], ph, vl);
                    mma8(o[nt], pl, vh);
                    mma8(o[nt], ph, vh);
                }
            }
        }
        __syncthreads();
    }

    // ---- normalize and store ----
    const float inv0 = 1.0f / l0;
    const float inv1 = 1.0f / l1;
    #pragma unroll
    for (int nt = 0; nt < 8; nt++) {
        const int col = h * HDIM + nt * 8 + 2 * tq;
        *(float2*)(g_A + (tok + r0) * DM + col) = make_float2(o[nt][0] * inv0, o[nt][1] * inv0);
        *(float2*)(g_A + (tok + r1) * DM + col) = make_float2(o[nt][2] * inv1, o[nt][3] * inv1);
    }
}

// ---------------------------------------------------------------------------
extern "C" void kernel_launch(void* const* d_in, const int* in_sizes, int n_in,
                              void* d_out, int out_size)
{
    (void)in_sizes; (void)n_in; (void)out_size;
    const float* x  = (const float*)d_in[0];
    const float* Wq = (const float*)d_in[1];
    const float* Wk = (const float*)d_in[2];
    const float* Wv = (const float*)d_in[3];
    const float* Wo = (const float*)d_in[4];
    const int*   tp = (const int*)d_in[6];
    float* out = (float*)d_out;

    cudaFuncSetAttribute(flash_attn_mma_kernel,
                         cudaFuncAttributeMaxDynamicSharedMemorySize, FLASH_SMEM);

    dim3 ggrid(DM / 128, MTOK / 128);   // (8, 32)
    gemm_tf32_kernel<true,  0, 0><<<ggrid, 128>>>(x, Wq, nullptr, tp);
    gemm_tf32_kernel<true,  0, 1><<<ggrid, 128>>>(x, Wk, nullptr, tp);
    gemm_tf32_kernel<false, 0, 2><<<ggrid, 128>>>(x, Wv, nullptr, tp);

    dim3 fgrid(SEQ / 128, 2 * NHEAD);   // (16, 32)
    flash_attn_mma_kernel<<<fgrid, 256, FLASH_SMEM>>>();

    gemm_tf32_kernel<false, 1, 3><<<ggrid, 128>>>(nullptr, Wo, out, tp);
}

// round 12
// speedup vs baseline: 2.1613x; 1.0063x over previous
#include <cuda_runtime.h>
#include <cuda_bf16.h>
#include <cstdint>

#define DM   1024
#define SEQ  2048
#define MTOK 4096   // BATCH*SEQ
#define NHEAD 16
#define HDIM 64

// Scratch (allocation-free rule: __device__ globals)
__device__ float g_Q[(size_t)MTOK * DM];
__device__ float g_K[(size_t)MTOK * DM];
__device__ float g_V[(size_t)MTOK * DM];
__device__ float g_A[(size_t)MTOK * DM];

// ---------------------------------------------------------------------------
// tf32 helpers
// ---------------------------------------------------------------------------
__device__ __forceinline__ uint32_t f2tf32(float x) {
    uint32_t u;
    asm("cvt.rna.tf32.f32 %0, %1;" : "=r"(u) : "f"(x));
    return u;
}

__device__ __forceinline__ void split2(float v, uint32_t& hi, uint32_t& lo) {
    uint32_t h = f2tf32(v);
    hi = h;
    lo = f2tf32(v - __uint_as_float(h));
}

__device__ __forceinline__ void split4(float4 v, float4& hi, float4& lo) {
    uint32_t h, l;
    split2(v.x, h, l); hi.x = __uint_as_float(h); lo.x = __uint_as_float(l);
    split2(v.y, h, l); hi.y = __uint_as_float(h); lo.y = __uint_as_float(l);
    split2(v.z, h, l); hi.z = __uint_as_float(h); lo.z = __uint_as_float(l);
    split2(v.w, h, l); hi.w = __uint_as_float(h); lo.w = __uint_as_float(l);
}

__device__ __forceinline__ void mma8(float* c, const uint32_t* a, const uint32_t* b) {
    asm volatile(
        "mma.sync.aligned.m16n8k8.row.col.f32.tf32.tf32.f32 "
        "{%0,%1,%2,%3}, {%4,%5,%6,%7}, {%8,%9}, {%0,%1,%2,%3};"
        : "+f"(c[0]), "+f"(c[1]), "+f"(c[2]), "+f"(c[3])
        : "r"(a[0]), "r"(a[1]), "r"(a[2]), "r"(a[3]), "r"(b[0]), "r"(b[1]));
}

// ---------------------------------------------------------------------------
// GEMM: C[m,n] = sum_k A[m,k] * W[n,k]  via 3-pass split tf32 (unchanged, R7).
// ---------------------------------------------------------------------------
#define BK 16
#define LDS_STRIDE 20

template<bool ROPE, int SRC, int DST>
__global__ __launch_bounds__(128, 2)
void gemm_tf32_kernel(const float* __restrict__ Aext, const float* __restrict__ W,
                      float* __restrict__ Cext, const int* __restrict__ tp)
{
    const float* A = (SRC == 0) ? Aext : g_A;
    float* C;
    if      (DST == 0) C = g_Q;
    else if (DST == 1) C = g_K;
    else if (DST == 2) C = g_V;
    else               C = Cext;

    __shared__ float Ah[128][LDS_STRIDE];
    __shared__ float Al[128][LDS_STRIDE];
    __shared__ float Bh[128][LDS_STRIDE];
    __shared__ float Bl[128][LDS_STRIDE];

    const int tid    = threadIdx.x;
    const int warp   = tid >> 5;
    const int lane   = tid & 31;
    const int group  = lane >> 2;
    const int tq     = lane & 3;
    const int warp_m = warp & 1;
    const int warp_n = warp >> 1;

    const int bm = blockIdx.y;
    const int bn = blockIdx.x;

    float c[4][8][4];
    #pragma unroll
    for (int mt = 0; mt < 4; mt++)
        #pragma unroll
        for (int nt = 0; nt < 8; nt++)
            #pragma unroll
            for (int r = 0; r < 4; r++)
                c[mt][nt][r] = 0.0f;

    const int lrow = tid >> 2;
    const int lc4  = (tid & 3) * 4;

    for (int k0 = 0; k0 < DM; k0 += BK) {
        #pragma unroll
        for (int i = 0; i < 4; i++) {
            const int row = lrow + i * 32;
            float4 av = *(const float4*)(A + (size_t)(bm * 128 + row) * DM + k0 + lc4);
            float4 wv = *(const float4*)(W + (size_t)(bn * 128 + row) * DM + k0 + lc4);

            float ax[4] = {av.x, av.y, av.z, av.w};
            float wx[4] = {wv.x, wv.y, wv.z, wv.w};
            #pragma unroll
            for (int e = 0; e < 4; e++) {
                uint32_t hu = f2tf32(ax[e]);
                float hf = __uint_as_float(hu);
                Ah[row][lc4 + e] = hf;
                Al[row][lc4 + e] = __uint_as_float(f2tf32(ax[e] - hf));
                uint32_t hw = f2tf32(wx[e]);
                float hwf = __uint_as_float(hw);
                Bh[row][lc4 + e] = hwf;
                Bl[row][lc4 + e] = __uint_as_float(f2tf32(wx[e] - hwf));
            }
        }
        __syncthreads();

        #pragma unroll
        for (int ks = 0; ks < 2; ks++) {
            const int kk = ks * 8 + tq;
            uint32_t ah[4][4], al[4][4];
            #pragma unroll
            for (int mt = 0; mt < 4; mt++) {
                const int r = warp_m * 64 + mt * 16 + group;
                ah[mt][0] = __float_as_uint(Ah[r][kk]);
                ah[mt][1] = __float_as_uint(Ah[r + 8][kk]);
                ah[mt][2] = __float_as_uint(Ah[r][kk + 4]);
                ah[mt][3] = __float_as_uint(Ah[r + 8][kk + 4]);
                al[mt][0] = __float_as_uint(Al[r][kk]);
                al[mt][1] = __float_as_uint(Al[r + 8][kk]);
                al[mt][2] = __float_as_uint(Al[r][kk + 4]);
                al[mt][3] = __float_as_uint(Al[r + 8][kk + 4]);
            }
            #pragma unroll
            for (int nt = 0; nt < 8; nt++) {
                const int n = warp_n * 64 + nt * 8 + group;
                uint32_t bh[2], bl[2];
                bh[0] = __float_as_uint(Bh[n][kk]);
                bh[1] = __float_as_uint(Bh[n][kk + 4]);
                bl[0] = __float_as_uint(Bl[n][kk]);
                bl[1] = __float_as_uint(Bl[n][kk + 4]);
                #pragma unroll
                for (int mt = 0; mt < 4; mt++) {
                    mma8(c[mt][nt], ah[mt], bl);
                    mma8(c[mt][nt], al[mt], bh);
                    mma8(c[mt][nt], ah[mt], bh);
                }
            }
        }
        __syncthreads();
    }

    const int rowbase = bm * 128 + warp_m * 64 + group;
    const int colbase = bn * 128 + warp_n * 64;

    #pragma unroll
    for (int mt = 0; mt < 4; mt++) {
        #pragma unroll
        for (int half = 0; half < 2; half++) {
            const int r = rowbase + mt * 16 + half * 8;
            float* crow = C + (size_t)r * DM;
            float pos = 0.0f;
            if (ROPE) pos = (float)tp[r & (SEQ - 1)];
            #pragma unroll
            for (int nt = 0; nt < 8; nt++) {
                const int col = colbase + nt * 8 + 2 * tq;
                float e = c[mt][nt][half * 2 + 0];
                float o = c[mt][nt][half * 2 + 1];
                if (ROPE) {
                    const int d_even = col & (HDIM - 1);
                    const float freq = expf(-(float)d_even * 0.14391156831212787f);
                    float s, cc;
                    sincosf(pos * freq, &s, &cc);
                    const float ne = e * cc - o * s;
                    const float no = e * s + o * cc;
                    e = ne; o = no;
                }
                *(float2*)(crow + col) = make_float2(e, o);
            }
        }
    }
}

// ---------------------------------------------------------------------------
// Flash attention, causal, tensor-core tf32 3-pass, pre-split K/V smem tiles.
// Block = 128 query rows; 256 threads = 8 warps x 16 rows; TWO blocks per SM
// (regs capped at 128 via launch_bounds; Q kept as fp32, split on the fly).
// ---------------------------------------------------------------------------
#define KS_STR 68
#define VS_STR 72
#define FLASH_SMEM ((2 * 64 * KS_STR + 2 * 64 * VS_STR) * 4)

__global__ __launch_bounds__(256, 2)
void flash_attn_mma_kernel()
{
    extern __shared__ float dsm[];
    float* Khi = dsm;
    float* Klo = Khi + 64 * KS_STR;
    float* Vhi = Klo + 64 * KS_STR;
    float* Vlo = Vhi + 64 * VS_STR;

    const int qt = blockIdx.x;     // 128-row query tile, 0..15
    const int bh = blockIdx.y;
    const int b  = bh >> 4;
    const int h  = bh & 15;

    const int tid  = threadIdx.x;
    const int w    = tid >> 5;     // 0..7
    const int lane = tid & 31;
    const int g    = lane >> 2;
    const int tq   = lane & 3;

    const int qbase = qt * 128;
    const int wlow  = qbase + w * 16;
    const int wmax  = wlow + 15;
    const int r0 = wlow + g;
    const int r1 = r0 + 8;
    const size_t tok = (size_t)b * SEQ;

    // Q fragments: scaled fp32, resident; tf32-split on the fly in S loop.
    float qf[8][4];
    #pragma unroll
    for (int ks = 0; ks < 8; ks++) {
        const int c0 = h * HDIM + ks * 8 + tq;
        qf[ks][0] = 0.125f * g_Q[(tok + r0) * DM + c0];
        qf[ks][1] = 0.125f * g_Q[(tok + r1) * DM + c0];
        qf[ks][2] = 0.125f * g_Q[(tok + r0) * DM + c0 + 4];
        qf[ks][3] = 0.125f * g_Q[(tok + r1) * DM + c0 + 4];
    }

    float o[8][4];
    #pragma unroll
    for (int nt = 0; nt < 8; nt++)
        #pragma unroll
        for (int e = 0; e < 4; e++) o[nt][e] = 0.0f;

    float m0 = -1e30f, m1 = -1e30f;
    float l0 = 0.0f,   l1 = 0.0f;

    const int ktmax = (qbase + 127) >> 6;

    for (int kt = 0; kt <= ktmax; ++kt) {
        // ---- cooperative load + tf32 pre-split of K,V tiles ----
        #pragma unroll
        for (int i = 0; i < 4; i++) {
            const int f  = tid + i * 256;
            const int r  = f >> 4;
            const int c4 = (f & 15) << 2;
            const size_t gidx = (tok + kt * 64 + r) * DM + h * HDIM + c4;
            float4 kv = *(const float4*)(g_K + gidx);
            float4 vv = *(const float4*)(g_V + gidx);
            float4 khi, klo, vhi, vlo;
            split4(kv, khi, klo);
            split4(vv, vhi, vlo);
            *(float4*)&Khi[r * KS_STR + c4] = khi;
            *(float4*)&Klo[r * KS_STR + c4] = klo;
            *(float4*)&Vhi[r * VS_STR + c4] = vhi;
            *(float4*)&Vlo[r * VS_STR + c4] = vlo;
        }
        __syncthreads();

        if (kt * 64 <= wmax) {   // uniform per warp: skip fully-masked tiles
            // ---- S = Q K^T (scaled), 3-pass tf32 ----
            float s[8][4];
            #pragma unroll
            for (int nt = 0; nt < 8; nt++)
                #pragma unroll
                for (int e = 0; e < 4; e++) s[nt][e] = 0.0f;

            #pragma unroll
            for (int ks = 0; ks < 8; ks++) {
                uint32_t qh[4], ql[4];
                split2(qf[ks][0], qh[0], ql[0]);
                split2(qf[ks][1], qh[1], ql[1]);
                split2(qf[ks][2], qh[2], ql[2]);
                split2(qf[ks][3], qh[3], ql[3]);
                #pragma unroll
                for (int nt = 0; nt < 8; nt++) {
                    const int base = (nt * 8 + g) * KS_STR + ks * 8 + tq;
                    uint32_t bhk[2], blk[2];
                    bhk[0] = __float_as_uint(Khi[base]);
                    bhk[1] = __float_as_uint(Khi[base + 4]);
                    blk[0] = __float_as_uint(Klo[base]);
                    blk[1] = __float_as_uint(Klo[base + 4]);
                    mma8(s[nt], qh, blk);
                    mma8(s[nt], ql, bhk);
                    mma8(s[nt], qh, bhk);
                }
            }

            // ---- causal mask (only tiles touching the diagonal) ----
            if (kt * 64 + 63 > wlow) {
                #pragma unroll
                for (int nt = 0; nt < 8; nt++) {
                    const int c = kt * 64 + nt * 8 + 2 * tq;
                    if (c     > r0) s[nt][0] = -1e30f;
                    if (c + 1 > r0) s[nt][1] = -1e30f;
                    if (c     > r1) s[nt][2] = -1e30f;
                    if (c + 1 > r1) s[nt][3] = -1e30f;
                }
            }

            // ---- online softmax (row stats via quad shuffles) ----
            float mx0 = -1e30f, mx1 = -1e30f;
            #pragma unroll
            for (int nt = 0; nt < 8; nt++) {
                mx0 = fmaxf(mx0, fmaxf(s[nt][0], s[nt][1]));
                mx1 = fmaxf(mx1, fmaxf(s[nt][2], s[nt][3]));
            }
            mx0 = fmaxf(mx0, __shfl_xor_sync(0xffffffffu, mx0, 1));
            mx0 = fmaxf(mx0, __shfl_xor_sync(0xffffffffu, mx0, 2));
            mx1 = fmaxf(mx1, __shfl_xor_sync(0xffffffffu, mx1, 1));
            mx1 = fmaxf(mx1, __shfl_xor_sync(0xffffffffu, mx1, 2));

            const float m0n = fmaxf(m0, mx0);
            const float m1n = fmaxf(m1, mx1);
            const float corr0 = __expf(m0 - m0n);
            const float corr1 = __expf(m1 - m1n);

            float sum0 = 0.0f, sum1 = 0.0f;
            #pragma unroll
            for (int nt = 0; nt < 8; nt++) {
                s[nt][0] = __expf(s[nt][0] - m0n); sum0 += s[nt][0];
                s[nt][1] = __expf(s[nt][1] - m0n); sum0 += s[nt][1];
                s[nt][2] = __expf(s[nt][2] - m1n); sum1 += s[nt][2];
                s[nt][3] = __expf(s[nt][3] - m1n); sum1 += s[nt][3];
            }
            sum0 += __shfl_xor_sync(0xffffffffu, sum0, 1);
            sum0 += __shfl_xor_sync(0xffffffffu, sum0, 2);
            sum1 += __shfl_xor_sync(0xffffffffu, sum1, 1);
            sum1 += __shfl_xor_sync(0xffffffffu, sum1, 2);
            l0 = l0 * corr0 + sum0;
            l1 = l1 * corr1 + sum1;
            m0 = m0n; m1 = m1n;

            #pragma unroll
            for (int nt = 0; nt < 8; nt++) {
                o[nt][0] *= corr0; o[nt][1] *= corr0;
                o[nt][2] *= corr1; o[nt][3] *= corr1;
            }

            // ---- O += P V, 3-pass tf32; permute P C-layout -> A-layout ----
            const int srcA = (lane & 28) | (tq >> 1);
            const int srcB = srcA | 2;
            const bool odd = (tq & 1);

            #pragma unroll
            for (int ks = 0; ks < 8; ks++) {
                const float pe  = __shfl_sync(0xffffffffu, s[ks][0], srcA);
                const float po  = __shfl_sync(0xffffffffu, s[ks][1], srcA);
                const float pe2 = __shfl_sync(0xffffffffu, s[ks][0], srcB);
                const float po2 = __shfl_sync(0xffffffffu, s[ks][1], srcB);
                const float re  = __shfl_sync(0xffffffffu, s[ks][2], srcA);
                const float ro  = __shfl_sync(0xffffffffu, s[ks][3], srcA);
                const float re2 = __shfl_sync(0xffffffffu, s[ks][2], srcB);
                const float ro2 = __shfl_sync(0xffffffffu, s[ks][3], srcB);

                uint32_t ph[4], pl[4];
                split2(odd ? po  : pe,  ph[0], pl[0]);
                split2(odd ? ro  : re,  ph[1], pl[1]);
                split2(odd ? po2 : pe2, ph[2], pl[2]);
                split2(odd ? ro2 : re2, ph[3], pl[3]);

                #pragma unroll
                for (int nt = 0; nt < 8; nt++) {
                    const int base = (ks * 8 + tq) * VS_STR + nt * 8 + g;
                    uint32_t vh[2], vl[2];
                    vh[0] = __float_as_uint(Vhi[base]);
                    vh[1] = __float_as_uint(Vhi[base + 4 * VS_STR]);
                    vl[0] = __float_as_uint(Vlo[base]);
                    vl[1] = __float_as_uint(Vlo[base + 4 * VS_STR]);
                    mma8(o[nt], ph, vl);
                    mma8(o[nt], pl, vh);
                    mma8(o[nt], ph, vh);
                }
            }
        }
        __syncthreads();
    }

    // ---- normalize and store ----
    const float inv0 = 1.0f / l0;
    const float inv1 = 1.0f / l1;
    #pragma unroll
    for (int nt = 0; nt < 8; nt++) {
        const int col = h * HDIM + nt * 8 + 2 * tq;
        *(float2*)(g_A + (tok + r0) * DM + col) = make_float2(o[nt][0] * inv0, o[nt][1] * inv0);
        *(float2*)(g_A + (tok + r1) * DM + col) = make_float2(o[nt][2] * inv1, o[nt][3] * inv1);
    }
}

// ---------------------------------------------------------------------------
extern "C" void kernel_launch(void* const* d_in, const int* in_sizes, int n_in,
                              void* d_out, int out_size)
{
    (void)in_sizes; (void)n_in; (void)out_size;
    const float* x  = (const float*)d_in[0];
    const float* Wq = (const float*)d_in[1];
    const float* Wk = (const float*)d_in[2];
    const float* Wv = (const float*)d_in[3];
    const float* Wo = (const float*)d_in[4];
    const int*   tp = (const int*)d_in[6];
    float* out = (float*)d_out;

    cudaFuncSetAttribute(flash_attn_mma_kernel,
                         cudaFuncAttributeMaxDynamicSharedMemorySize, FLASH_SMEM);

    dim3 ggrid(DM / 128, MTOK / 128);   // (8, 32)
    gemm_tf32_kernel<true,  0, 0><<<ggrid, 128>>>(x, Wq, nullptr, tp);
    gemm_tf32_kernel<true,  0, 1><<<ggrid, 128>>>(x, Wk, nullptr, tp);
    gemm_tf32_kernel<false, 0, 2><<<ggrid, 128>>>(x, Wv, nullptr, tp);

    dim3 fgrid(SEQ / 128, 2 * NHEAD);   // (16, 32)
    flash_attn_mma_kernel<<<fgrid, 256, FLASH_SMEM>>>();

    gemm_tf32_kernel<false, 1, 3><<<ggrid, 128>>>(nullptr, Wo, out, tp);
}

// round 13
// speedup vs baseline: 3.1293x; 1.4479x over previous
#include <cuda_runtime.h>
#include <cuda_bf16.h>
#include <cstdint>

#define DM   1024
#define SEQ  2048
#define MTOK 4096   // BATCH*SEQ
#define NHEAD 16
#define HDIM 64

// Scratch (allocation-free rule: __device__ globals)
__device__ float g_Q[(size_t)MTOK * DM];
__device__ float g_K[(size_t)MTOK * DM];
__device__ float g_V[(size_t)MTOK * DM];
__device__ float g_A[(size_t)MTOK * DM];

// ---------------------------------------------------------------------------
// bf16 split helpers: x ≈ hi + lo, both bf16 (≈16-bit effective mantissa)
// ---------------------------------------------------------------------------
__device__ __forceinline__ void bsplit(float x, uint16_t& hi, uint16_t& lo) {
    __nv_bfloat16 h = __float2bfloat16(x);
    float r = x - __bfloat162float(h);
    __nv_bfloat16 l = __float2bfloat16(r);
    hi = *reinterpret_cast<uint16_t*>(&h);
    lo = *reinterpret_cast<uint16_t*>(&l);
}

// pack two adjacent-k values into one bf16x2 word (low half = first element)
__device__ __forceinline__ void bsplit2(float x, float y, uint32_t& hi, uint32_t& lo) {
    uint16_t hx, lx, hy, ly;
    bsplit(x, hx, lx);
    bsplit(y, hy, ly);
    hi = (uint32_t)hx | ((uint32_t)hy << 16);
    lo = (uint32_t)lx | ((uint32_t)ly << 16);
}

__device__ __forceinline__ void mma16(float* c, const uint32_t* a, const uint32_t* b) {
    asm volatile(
        "mma.sync.aligned.m16n8k16.row.col.f32.bf16.bf16.f32 "
        "{%0,%1,%2,%3}, {%4,%5,%6,%7}, {%8,%9}, {%0,%1,%2,%3};"
        : "+f"(c[0]), "+f"(c[1]), "+f"(c[2]), "+f"(c[3])
        : "r"(a[0]), "r"(a[1]), "r"(a[2]), "r"(a[3]), "r"(b[0]), "r"(b[1]));
}

// ---------------------------------------------------------------------------
// GEMM: C[m,n] = sum_k A[m,k] * W[n,k]  via 3-pass split bf16 mma (k16).
// BM=BN=128, BK=16, 128 threads = 4 warps (2x2), warp tile 64x64.
// SMEM pair arrays stride 12 (8 pairs + 4 pad): fragment reads conflict-free.
// ---------------------------------------------------------------------------
#define BK 16
#define GP_STR 12   // pairs stride

template<bool ROPE, int SRC, int DST>
__global__ __launch_bounds__(128, 2)
void gemm_bf16_kernel(const float* __restrict__ Aext, const float* __restrict__ W,
                      float* __restrict__ Cext, const int* __restrict__ tp)
{
    const float* A = (SRC == 0) ? Aext : g_A;
    float* C;
    if      (DST == 0) C = g_Q;
    else if (DST == 1) C = g_K;
    else if (DST == 2) C = g_V;
    else               C = Cext;

    __shared__ uint32_t Ah[128][GP_STR];
    __shared__ uint32_t Al[128][GP_STR];
    __shared__ uint32_t Bh[128][GP_STR];
    __shared__ uint32_t Bl[128][GP_STR];

    const int tid    = threadIdx.x;
    const int warp   = tid >> 5;
    const int lane   = tid & 31;
    const int group  = lane >> 2;
    const int tq     = lane & 3;
    const int warp_m = warp & 1;
    const int warp_n = warp >> 1;

    const int bm = blockIdx.y;
    const int bn = blockIdx.x;

    float c[4][8][4];
    #pragma unroll
    for (int mt = 0; mt < 4; mt++)
        #pragma unroll
        for (int nt = 0; nt < 8; nt++)
            #pragma unroll
            for (int r = 0; r < 4; r++)
                c[mt][nt][r] = 0.0f;

    const int lrow = tid >> 2;          // 0..31
    const int lc4  = (tid & 3) * 4;     // 0,4,8,12
    const int lpr  = (tid & 3) * 2;     // pair index 0,2,4,6

    for (int k0 = 0; k0 < DM; k0 += BK) {
        #pragma unroll
        for (int i = 0; i < 4; i++) {
            const int row = lrow + i * 32;
            float4 av = *(const float4*)(A + (size_t)(bm * 128 + row) * DM + k0 + lc4);
            float4 wv = *(const float4*)(W + (size_t)(bn * 128 + row) * DM + k0 + lc4);
            uint32_t h0, l0, h1, l1;
            bsplit2(av.x, av.y, h0, l0);
            bsplit2(av.z, av.w, h1, l1);
            *(uint2*)&Ah[row][lpr] = make_uint2(h0, h1);
            *(uint2*)&Al[row][lpr] = make_uint2(l0, l1);
            bsplit2(wv.x, wv.y, h0, l0);
            bsplit2(wv.z, wv.w, h1, l1);
            *(uint2*)&Bh[row][lpr] = make_uint2(h0, h1);
            *(uint2*)&Bl[row][lpr] = make_uint2(l0, l1);
        }
        __syncthreads();

        uint32_t ah[4][4], al[4][4];
        #pragma unroll
        for (int mt = 0; mt < 4; mt++) {
            const int r = warp_m * 64 + mt * 16 + group;
            ah[mt][0] = Ah[r][tq];
            ah[mt][1] = Ah[r + 8][tq];
            ah[mt][2] = Ah[r][tq + 4];
            ah[mt][3] = Ah[r + 8][tq + 4];
            al[mt][0] = Al[r][tq];
            al[mt][1] = Al[r + 8][tq];
            al[mt][2] = Al[r][tq + 4];
            al[mt][3] = Al[r + 8][tq + 4];
        }
        #pragma unroll
        for (int nt = 0; nt < 8; nt++) {
            const int n = warp_n * 64 + nt * 8 + group;
            uint32_t bh[2], bl[2];
            bh[0] = Bh[n][tq];
            bh[1] = Bh[n][tq + 4];
            bl[0] = Bl[n][tq];
            bl[1] = Bl[n][tq + 4];
            #pragma unroll
            for (int mt = 0; mt < 4; mt++) {
                mma16(c[mt][nt], ah[mt], bl);
                mma16(c[mt][nt], al[mt], bh);
                mma16(c[mt][nt], ah[mt], bh);
            }
        }
        __syncthreads();
    }

    const int rowbase = bm * 128 + warp_m * 64 + group;
    const int colbase = bn * 128 + warp_n * 64;

    #pragma unroll
    for (int mt = 0; mt < 4; mt++) {
        #pragma unroll
        for (int half = 0; half < 2; half++) {
            const int r = rowbase + mt * 16 + half * 8;
            float* crow = C + (size_t)r * DM;
            float pos = 0.0f;
            if (ROPE) pos = (float)tp[r & (SEQ - 1)];
            #pragma unroll
            for (int nt = 0; nt < 8; nt++) {
                const int col = colbase + nt * 8 + 2 * tq;
                float e = c[mt][nt][half * 2 + 0];
                float o = c[mt][nt][half * 2 + 1];
                if (ROPE) {
                    const int d_even = col & (HDIM - 1);
                    const float freq = expf(-(float)d_even * 0.14391156831212787f);
                    float s, cc;
                    sincosf(pos * freq, &s, &cc);
                    const float ne = e * cc - o * s;
                    const float no = e * s + o * cc;
                    e = ne; o = no;
                }
                *(float2*)(crow + col) = make_float2(e, o);
            }
        }
    }
}

// ---------------------------------------------------------------------------
// Flash attention, causal, bf16 3-pass mma (k16), pre-split packed smem tiles.
// Block = 128 query rows; 256 threads = 8 warps x 16 rows; 2 blocks/SM.
// K packed along d: Khi/Klo[key][d-pair], stride 36 (reads 4g+tq: no conflict).
// V packed along keys, TRANSPOSED: Vhi/Vlo[d][key-pair], stride 36.
// PV A-fragments come straight from S C-fragments (no shuffles needed).
// ---------------------------------------------------------------------------
#define FP_STR 36   // 32 pairs + 4 pad

__global__ __launch_bounds__(256, 2)
void flash_attn_mma_kernel()
{
    __shared__ uint32_t Khi[64 * FP_STR];
    __shared__ uint32_t Klo[64 * FP_STR];
    __shared__ uint32_t Vhi[64 * FP_STR];
    __shared__ uint32_t Vlo[64 * FP_STR];

    const int qt = blockIdx.x;     // 128-row query tile, 0..15
    const int bh = blockIdx.y;
    const int b  = bh >> 4;
    const int h  = bh & 15;

    const int tid  = threadIdx.x;
    const int w    = tid >> 5;
    const int lane = tid & 31;
    const int g    = lane >> 2;
    const int tq   = lane & 3;

    const int qbase = qt * 128;
    const int wlow  = qbase + w * 16;
    const int wmax  = wlow + 15;
    const int r0 = wlow + g;
    const int r1 = r0 + 8;
    const size_t tok = (size_t)b * SEQ;

    // Q fragments: scaled, bf16 hi/lo split, packed pairs. 4 k16-steps.
    uint32_t qh[4][4], ql[4][4];
    #pragma unroll
    for (int ks = 0; ks < 4; ks++) {
        const int c0 = h * HDIM + ks * 16 + 2 * tq;
        float2 a = *(const float2*)(g_Q + (tok + r0) * DM + c0);
        float2 bq = *(const float2*)(g_Q + (tok + r1) * DM + c0);
        float2 cq = *(const float2*)(g_Q + (tok + r0) * DM + c0 + 8);
        float2 d = *(const float2*)(g_Q + (tok + r1) * DM + c0 + 8);
        bsplit2(0.125f * a.x,  0.125f * a.y,  qh[ks][0], ql[ks][0]);
        bsplit2(0.125f * bq.x, 0.125f * bq.y, qh[ks][1], ql[ks][1]);
        bsplit2(0.125f * cq.x, 0.125f * cq.y, qh[ks][2], ql[ks][2]);
        bsplit2(0.125f * d.x,  0.125f * d.y,  qh[ks][3], ql[ks][3]);
    }

    float o[8][4];
    #pragma unroll
    for (int nt = 0; nt < 8; nt++)
        #pragma unroll
        for (int e = 0; e < 4; e++) o[nt][e] = 0.0f;

    float m0 = -1e30f, m1 = -1e30f;
    float l0 = 0.0f,   l1 = 0.0f;

    const int ktmax = (qbase + 127) >> 6;

    for (int kt = 0; kt <= ktmax; ++kt) {
        // ---- cooperative load + bf16 split/pack of K (row-packed) and
        //      V (transposed, key-packed) ----
        #pragma unroll
        for (int i = 0; i < 4; i++) {
            const int f  = tid + i * 256;
            const int r  = f >> 4;              // key row 0..63
            const int c4 = (f & 15) << 2;       // d offset 0..60
            const size_t gidx = (tok + kt * 64 + r) * DM + h * HDIM + c4;
            float4 kv = *(const float4*)(g_K + gidx);
            float4 vv = *(const float4*)(g_V + gidx);

            uint32_t h0, l0v, h1, l1v;
            bsplit2(kv.x, kv.y, h0, l0v);
            bsplit2(kv.z, kv.w, h1, l1v);
            *(uint2*)&Khi[r * FP_STR + (c4 >> 1)] = make_uint2(h0, h1);
            *(uint2*)&Klo[r * FP_STR + (c4 >> 1)] = make_uint2(l0v, l1v);

            // V transpose: element (key=r, d=c4+e) -> half (r&1) of word
            // Vhi[(c4+e)*FP_STR + (r>>1)]
            const int kp = r >> 1;
            const int hf = r & 1;
            float ve[4] = {vv.x, vv.y, vv.z, vv.w};
            #pragma unroll
            for (int e = 0; e < 4; e++) {
                uint16_t hb, lb;
                bsplit(ve[e], hb, lb);
                ((uint16_t*)(Vhi + (c4 + e) * FP_STR + kp))[hf] = hb;
                ((uint16_t*)(Vlo + (c4 + e) * FP_STR + kp))[hf] = lb;
            }
        }
        __syncthreads();

        if (kt * 64 <= wmax) {   // uniform per warp: skip fully-masked tiles
            // ---- S = Q K^T (scaled), 3-pass bf16, 4 k16-steps ----
            float s[8][4];
            #pragma unroll
            for (int nt = 0; nt < 8; nt++)
                #pragma unroll
                for (int e = 0; e < 4; e++) s[nt][e] = 0.0f;

            #pragma unroll
            for (int ks = 0; ks < 4; ks++) {
                #pragma unroll
                for (int nt = 0; nt < 8; nt++) {
                    const int base = (nt * 8 + g) * FP_STR + ks * 8 + tq;
                    uint32_t bhk[2], blk[2];
                    bhk[0] = Khi[base];
                    bhk[1] = Khi[base + 4];
                    blk[0] = Klo[base];
                    blk[1] = Klo[base + 4];
                    mma16(s[nt], qh[ks], blk);
                    mma16(s[nt], ql[ks], bhk);
                    mma16(s[nt], qh[ks], bhk);
                }
            }

            // ---- causal mask (only tiles touching the diagonal) ----
            if (kt * 64 + 63 > wlow) {
                #pragma unroll
                for (int nt = 0; nt < 8; nt++) {
                    const int c = kt * 64 + nt * 8 + 2 * tq;
                    if (c     > r0) s[nt][0] = -1e30f;
                    if (c + 1 > r0) s[nt][1] = -1e30f;
                    if (c     > r1) s[nt][2] = -1e30f;
                    if (c + 1 > r1) s[nt][3] = -1e30f;
                }
            }

            // ---- online softmax (row stats via quad shuffles) ----
            float mx0 = -1e30f, mx1 = -1e30f;
            #pragma unroll
            for (int nt = 0; nt < 8; nt++) {
                mx0 = fmaxf(mx0, fmaxf(s[nt][0], s[nt][1]));
                mx1 = fmaxf(mx1, fmaxf(s[nt][2], s[nt][3]));
            }
            mx0 = fmaxf(mx0, __shfl_xor_sync(0xffffffffu, mx0, 1));
            mx0 = fmaxf(mx0, __shfl_xor_sync(0xffffffffu, mx0, 2));
            mx1 = fmaxf(mx1, __shfl_xor_sync(0xffffffffu, mx1, 1));
            mx1 = fmaxf(mx1, __shfl_xor_sync(0xffffffffu, mx1, 2));

            const float m0n = fmaxf(m0, mx0);
            const float m1n = fmaxf(m1, mx1);
            const float corr0 = __expf(m0 - m0n);
            const float corr1 = __expf(m1 - m1n);

            float sum0 = 0.0f, sum1 = 0.0f;
            #pragma unroll
            for (int nt = 0; nt < 8; nt++) {
                s[nt][0] = __expf(s[nt][0] - m0n); sum0 += s[nt][0];
                s[nt][1] = __expf(s[nt][1] - m0n); sum0 += s[nt][1];
                s[nt][2] = __expf(s[nt][2] - m1n); sum1 += s[nt][2];
                s[nt][3] = __expf(s[nt][3] - m1n); sum1 += s[nt][3];
            }
            sum0 += __shfl_xor_sync(0xffffffffu, sum0, 1);
            sum0 += __shfl_xor_sync(0xffffffffu, sum0, 2);
            sum1 += __shfl_xor_sync(0xffffffffu, sum1, 1);
            sum1 += __shfl_xor_sync(0xffffffffu, sum1, 2);
            l0 = l0 * corr0 + sum0;
            l1 = l1 * corr1 + sum1;
            m0 = m0n; m1 = m1n;

            #pragma unroll
            for (int nt = 0; nt < 8; nt++) {
                o[nt][0] *= corr0; o[nt][1] *= corr0;
                o[nt][2] *= corr1; o[nt][3] *= corr1;
            }

            // ---- O += P V, 3-pass bf16. S C-frag cols (2tq,2tq+1) ARE the
            //      A-frag k-pairs: pack in-lane, zero shuffles. ----
            #pragma unroll
            for (int ks = 0; ks < 4; ks++) {
                uint32_t ph[4], pl[4];
                bsplit2(s[2 * ks][0],     s[2 * ks][1],     ph[0], pl[0]);
                bsplit2(s[2 * ks][2],     s[2 * ks][3],     ph[1], pl[1]);
                bsplit2(s[2 * ks + 1][0], s[2 * ks + 1][1], ph[2], pl[2]);
                bsplit2(s[2 * ks + 1][2], s[2 * ks + 1][3], ph[3], pl[3]);

                #pragma unroll
                for (int nt = 0; nt < 8; nt++) {
                    const int base = (nt * 8 + g) * FP_STR + ks * 8 + tq;
                    uint32_t vh[2], vl[2];
                    vh[0] = Vhi[base];
                    vh[1] = Vhi[base + 4];
                    vl[0] = Vlo[base];
                    vl[1] = Vlo[base + 4];
                    mma16(o[nt], ph, vl);
                    mma16(o[nt], pl, vh);
                    mma16(o[nt], ph, vh);
                }
            }
        }
        __syncthreads();
    }

    // ---- normalize and store ----
    const float inv0 = 1.0f / l0;
    const float inv1 = 1.0f / l1;
    #pragma unroll
    for (int nt = 0; nt < 8; nt++) {
        const int col = h * HDIM + nt * 8 + 2 * tq;
        *(float2*)(g_A + (tok + r0) * DM + col) = make_float2(o[nt][0] * inv0, o[nt][1] * inv0);
        *(float2*)(g_A + (tok + r1) * DM + col) = make_float2(o[nt][2] * inv1, o[nt][3] * inv1);
    }
}

// ---------------------------------------------------------------------------
extern "C" void kernel_launch(void* const* d_in, const int* in_sizes, int n_in,
                              void* d_out, int out_size)
{
    (void)in_sizes; (void)n_in; (void)out_size;
    const float* x  = (const float*)d_in[0];
    const float* Wq = (const float*)d_in[1];
    const float* Wk = (const float*)d_in[2];
    const float* Wv = (const float*)d_in[3];
    const float* Wo = (const float*)d_in[4];
    const int*   tp = (const int*)d_in[6];
    float* out = (float*)d_out;

    dim3 ggrid(DM / 128, MTOK / 128);   // (8, 32)
    gemm_bf16_kernel<true,  0, 0><<<ggrid, 128>>>(x, Wq, nullptr, tp);
    gemm_bf16_kernel<true,  0, 1><<<ggrid, 128>>>(x, Wk, nullptr, tp);
    gemm_bf16_kernel<false, 0, 2><<<ggrid, 128>>>(x, Wv, nullptr, tp);

    dim3 fgrid(SEQ / 128, 2 * NHEAD);   // (16, 32)
    flash_attn_mma_kernel<<<fgrid, 256>>>();

    gemm_bf16_kernel<false, 1, 3><<<ggrid, 128>>>(nullptr, Wo, out, tp);
}

// round 16
// speedup vs baseline: 3.4413x; 1.0997x over previous
#include <cuda_runtime.h>
#include <cuda_bf16.h>
#include <cstdint>

#define DM   1024
#define SEQ  2048
#define MTOK 4096   // BATCH*SEQ
#define NHEAD 16
#define HDIM 64

// Scratch (allocation-free rule: __device__ globals)
__device__ float g_Q[(size_t)MTOK * DM];
__device__ float g_K[(size_t)MTOK * DM];
__device__ float g_V[(size_t)MTOK * DM];
__device__ float g_A[(size_t)MTOK * DM];

// ---------------------------------------------------------------------------
// bf16 split helpers: x ≈ hi + lo, both bf16 (≈16-bit effective mantissa)
// ---------------------------------------------------------------------------
__device__ __forceinline__ void bsplit(float x, uint16_t& hi, uint16_t& lo) {
    __nv_bfloat16 h = __float2bfloat16(x);
    float r = x - __bfloat162float(h);
    __nv_bfloat16 l = __float2bfloat16(r);
    hi = *reinterpret_cast<uint16_t*>(&h);
    lo = *reinterpret_cast<uint16_t*>(&l);
}

// pack two adjacent-k values into one bf16x2 word (low half = first element)
__device__ __forceinline__ void bsplit2(float x, float y, uint32_t& hi, uint32_t& lo) {
    uint16_t hx, lx, hy, ly;
    bsplit(x, hx, lx);
    bsplit(y, hy, ly);
    hi = (uint32_t)hx | ((uint32_t)hy << 16);
    lo = (uint32_t)lx | ((uint32_t)ly << 16);
}

__device__ __forceinline__ void mma16(float* c, const uint32_t* a, const uint32_t* b) {
    asm volatile(
        "mma.sync.aligned.m16n8k16.row.col.f32.bf16.bf16.f32 "
        "{%0,%1,%2,%3}, {%4,%5,%6,%7}, {%8,%9}, {%0,%1,%2,%3};"
        : "+f"(c[0]), "+f"(c[1]), "+f"(c[2]), "+f"(c[3])
        : "r"(a[0]), "r"(a[1]), "r"(a[2]), "r"(a[3]), "r"(b[0]), "r"(b[1]));
}

__device__ __forceinline__ void ldsm4t(uint32_t* r, uint32_t smem_addr) {
    asm volatile(
        "ldmatrix.sync.aligned.m8n8.x4.trans.shared.b16 {%0,%1,%2,%3}, [%4];"
        : "=r"(r[0]), "=r"(r[1]), "=r"(r[2]), "=r"(r[3])
        : "r"(smem_addr));
}

// ---------------------------------------------------------------------------
// GEMM: C[m,n] = sum_k A[m,k] * W[n,k]  via 3-pass split bf16 mma (k16).
// (unchanged from R13)
// ---------------------------------------------------------------------------
#define BK 16
#define GP_STR 12   // pairs stride

template<bool ROPE, int SRC, int DST>
__global__ __launch_bounds__(128, 2)
void gemm_bf16_kernel(const float* __restrict__ Aext, const float* __restrict__ W,
                      float* __restrict__ Cext, const int* __restrict__ tp)
{
    const float* A = (SRC == 0) ? Aext : g_A;
    float* C;
    if      (DST == 0) C = g_Q;
    else if (DST == 1) C = g_K;
    else if (DST == 2) C = g_V;
    else               C = Cext;

    __shared__ uint32_t Ah[128][GP_STR];
    __shared__ uint32_t Al[128][GP_STR];
    __shared__ uint32_t Bh[128][GP_STR];
    __shared__ uint32_t Bl[128][GP_STR];

    const int tid    = threadIdx.x;
    const int warp   = tid >> 5;
    const int lane   = tid & 31;
    const int group  = lane >> 2;
    const int tq     = lane & 3;
    const int warp_m = warp & 1;
    const int warp_n = warp >> 1;

    const int bm = blockIdx.y;
    const int bn = blockIdx.x;

    float c[4][8][4];
    #pragma unroll
    for (int mt = 0; mt < 4; mt++)
        #pragma unroll
        for (int nt = 0; nt < 8; nt++)
            #pragma unroll
            for (int r = 0; r < 4; r++)
                c[mt][nt][r] = 0.0f;

    const int lrow = tid >> 2;          // 0..31
    const int lc4  = (tid & 3) * 4;     // 0,4,8,12
    const int lpr  = (tid & 3) * 2;     // pair index 0,2,4,6

    for (int k0 = 0; k0 < DM; k0 += BK) {
        #pragma unroll
        for (int i = 0; i < 4; i++) {
            const int row = lrow + i * 32;
            float4 av = *(const float4*)(A + (size_t)(bm * 128 + row) * DM + k0 + lc4);
            float4 wv = *(const float4*)(W + (size_t)(bn * 128 + row) * DM + k0 + lc4);
            uint32_t h0, l0, h1, l1;
            bsplit2(av.x, av.y, h0, l0);
            bsplit2(av.z, av.w, h1, l1);
            *(uint2*)&Ah[row][lpr] = make_uint2(h0, h1);
            *(uint2*)&Al[row][lpr] = make_uint2(l0, l1);
            bsplit2(wv.x, wv.y, h0, l0);
            bsplit2(wv.z, wv.w, h1, l1);
            *(uint2*)&Bh[row][lpr] = make_uint2(h0, h1);
            *(uint2*)&Bl[row][lpr] = make_uint2(l0, l1);
        }
        __syncthreads();

        uint32_t ah[4][4], al[4][4];
        #pragma unroll
        for (int mt = 0; mt < 4; mt++) {
            const int r = warp_m * 64 + mt * 16 + group;
            ah[mt][0] = Ah[r][tq];
            ah[mt][1] = Ah[r + 8][tq];
            ah[mt][2] = Ah[r][tq + 4];
            ah[mt][3] = Ah[r + 8][tq + 4];
            al[mt][0] = Al[r][tq];
            al[mt][1] = Al[r + 8][tq];
            al[mt][2] = Al[r][tq + 4];
            al[mt][3] = Al[r + 8][tq + 4];
        }
        #pragma unroll
        for (int nt = 0; nt < 8; nt++) {
            const int n = warp_n * 64 + nt * 8 + group;
            uint32_t bh[2], bl[2];
            bh[0] = Bh[n][tq];
            bh[1] = Bh[n][tq + 4];
            bl[0] = Bl[n][tq];
            bl[1] = Bl[n][tq + 4];
            #pragma unroll
            for (int mt = 0; mt < 4; mt++) {
                mma16(c[mt][nt], ah[mt], bl);
                mma16(c[mt][nt], al[mt], bh);
                mma16(c[mt][nt], ah[mt], bh);
            }
        }
        __syncthreads();
    }

    const int rowbase = bm * 128 + warp_m * 64 + group;
    const int colbase = bn * 128 + warp_n * 64;

    #pragma unroll
    for (int mt = 0; mt < 4; mt++) {
        #pragma unroll
        for (int half = 0; half < 2; half++) {
            const int r = rowbase + mt * 16 + half * 8;
            float* crow = C + (size_t)r * DM;
            float pos = 0.0f;
            if (ROPE) pos = (float)tp[r & (SEQ - 1)];
            #pragma unroll
            for (int nt = 0; nt < 8; nt++) {
                const int col = colbase + nt * 8 + 2 * tq;
                float e = c[mt][nt][half * 2 + 0];
                float o = c[mt][nt][half * 2 + 1];
                if (ROPE) {
                    const int d_even = col & (HDIM - 1);
                    const float freq = expf(-(float)d_even * 0.14391156831212787f);
                    float s, cc;
                    sincosf(pos * freq, &s, &cc);
                    const float ne = e * cc - o * s;
                    const float no = e * s + o * cc;
                    e = ne; o = no;
                }
                *(float2*)(crow + col) = make_float2(e, o);
            }
        }
    }
}

// ---------------------------------------------------------------------------
// Flash attention, causal, bf16 3-pass mma (k16).
// K AND V both stored row-packed (key-major, bf16 d-pairs, stride 36 words):
// conflict-free uint2 stores. PV B-fragments (V transposed) produced via
// ldmatrix.m8n8.x4.trans.b16 — row pointers hit banks 4·key mod 32, conflict-
// free. No scatter stores, no shuffles in PV (S C-frag cols are A-frag pairs).
// Block = 128 query rows; 256 threads = 8 warps x 16 rows; 2 blocks/SM.
// ---------------------------------------------------------------------------
#define FP_STR 36   // 32 pairs + 4 pad

__global__ __launch_bounds__(256, 2)
void flash_attn_mma_kernel()
{
    __shared__ uint32_t Khi[64 * FP_STR];
    __shared__ uint32_t Klo[64 * FP_STR];
    __shared__ uint32_t Vhi[64 * FP_STR];
    __shared__ uint32_t Vlo[64 * FP_STR];

    const int qt = (int)gridDim.x - 1 - (int)blockIdx.x;  // heavy tiles first
    const int bh = blockIdx.y;
    const int b  = bh >> 4;
    const int h  = bh & 15;

    const int tid  = threadIdx.x;
    const int w    = tid >> 5;
    const int lane = tid & 31;
    const int g    = lane >> 2;
    const int tq   = lane & 3;

    const int qbase = qt * 128;
    const int wlow  = qbase + w * 16;
    const int wmax  = wlow + 15;
    const int r0 = wlow + g;
    const int r1 = r0 + 8;
    const size_t tok = (size_t)b * SEQ;

    // ldmatrix per-lane base (word units into V arrays):
    // lanes 0-7: mat0 rows (keys +0), 8-15: mat1 (keys +8),
    // 16-23: mat2 (d +8 -> pair +4), 24-31: mat3 (keys+8, d+8)
    const int lrow8 = lane & 7;
    const int grpK  = (lane >> 3) & 1;
    const int grpD  = lane >> 4;
    const uint32_t vlane = (uint32_t)((lrow8 + 8 * grpK) * FP_STR + 4 * grpD) * 4u;
    const uint32_t vhi_base = (uint32_t)__cvta_generic_to_shared(Vhi) + vlane;
    const uint32_t vlo_base = (uint32_t)__cvta_generic_to_shared(Vlo) + vlane;

    // Q fragments: scaled, bf16 hi/lo split, packed pairs. 4 k16-steps.
    uint32_t qh[4][4], ql[4][4];
    #pragma unroll
    for (int ks = 0; ks < 4; ks++) {
        const int c0 = h * HDIM + ks * 16 + 2 * tq;
        float2 a  = *(const float2*)(g_Q + (tok + r0) * DM + c0);
        float2 bq = *(const float2*)(g_Q + (tok + r1) * DM + c0);
        float2 cq = *(const float2*)(g_Q + (tok + r0) * DM + c0 + 8);
        float2 d  = *(const float2*)(g_Q + (tok + r1) * DM + c0 + 8);
        bsplit2(0.125f * a.x,  0.125f * a.y,  qh[ks][0], ql[ks][0]);
        bsplit2(0.125f * bq.x, 0.125f * bq.y, qh[ks][1], ql[ks][1]);
        bsplit2(0.125f * cq.x, 0.125f * cq.y, qh[ks][2], ql[ks][2]);
        bsplit2(0.125f * d.x,  0.125f * d.y,  qh[ks][3], ql[ks][3]);
    }

    float o[8][4];
    #pragma unroll
    for (int nt = 0; nt < 8; nt++)
        #pragma unroll
        for (int e = 0; e < 4; e++) o[nt][e] = 0.0f;

    float m0 = -1e30f, m1 = -1e30f;
    float l0 = 0.0f,   l1 = 0.0f;

    const int ktmax = (qbase + 127) >> 6;

    for (int kt = 0; kt <= ktmax; ++kt) {
        // ---- cooperative load + bf16 split/pack; K and V identical layout ----
        #pragma unroll
        for (int i = 0; i < 4; i++) {
            const int f  = tid + i * 256;
            const int r  = f >> 4;              // key row 0..63
            const int c4 = (f & 15) << 2;       // d offset 0..60
            const size_t gidx = (tok + kt * 64 + r) * DM + h * HDIM + c4;
            float4 kv = *(const float4*)(g_K + gidx);
            float4 vv = *(const float4*)(g_V + gidx);

            uint32_t h0, l0v, h1, l1v;
            bsplit2(kv.x, kv.y, h0, l0v);
            bsplit2(kv.z, kv.w, h1, l1v);
            *(uint2*)&Khi[r * FP_STR + (c4 >> 1)] = make_uint2(h0, h1);
            *(uint2*)&Klo[r * FP_STR + (c4 >> 1)] = make_uint2(l0v, l1v);

            bsplit2(vv.x, vv.y, h0, l0v);
            bsplit2(vv.z, vv.w, h1, l1v);
            *(uint2*)&Vhi[r * FP_STR + (c4 >> 1)] = make_uint2(h0, h1);
            *(uint2*)&Vlo[r * FP_STR + (c4 >> 1)] = make_uint2(l0v, l1v);
        }
        __syncthreads();

        if (kt * 64 <= wmax) {   // uniform per warp: skip fully-masked tiles
            // ---- S = Q K^T (scaled), 3-pass bf16, 4 k16-steps ----
            float s[8][4];
            #pragma unroll
            for (int nt = 0; nt < 8; nt++)
                #pragma unroll
                for (int e = 0; e < 4; e++) s[nt][e] = 0.0f;

            #pragma unroll
            for (int ks = 0; ks < 4; ks++) {
                #pragma unroll
                for (int nt = 0; nt < 8; nt++) {
                    const int base = (nt * 8 + g) * FP_STR + ks * 8 + tq;
                    uint32_t bhk[2], blk[2];
                    bhk[0] = Khi[base];
                    bhk[1] = Khi[base + 4];
                    blk[0] = Klo[base];
                    blk[1] = Klo[base + 4];
                    mma16(s[nt], qh[ks], blk);
                    mma16(s[nt], ql[ks], bhk);
                    mma16(s[nt], qh[ks], bhk);
                }
            }

            // ---- causal mask (only tiles touching the diagonal) ----
            if (kt * 64 + 63 > wlow) {
                #pragma unroll
                for (int nt = 0; nt < 8; nt++) {
                    const int c = kt * 64 + nt * 8 + 2 * tq;
                    if (c     > r0) s[nt][0] = -1e30f;
                    if (c + 1 > r0) s[nt][1] = -1e30f;
                    if (c     > r1) s[nt][2] = -1e30f;
                    if (c + 1 > r1) s[nt][3] = -1e30f;
                }
            }

            // ---- online softmax (row stats via quad shuffles) ----
            float mx0 = -1e30f, mx1 = -1e30f;
            #pragma unroll
            for (int nt = 0; nt < 8; nt++) {
                mx0 = fmaxf(mx0, fmaxf(s[nt][0], s[nt][1]));
                mx1 = fmaxf(mx1, fmaxf(s[nt][2], s[nt][3]));
            }
            mx0 = fmaxf(mx0, __shfl_xor_sync(0xffffffffu, mx0, 1));
            mx0 = fmaxf(mx0, __shfl_xor_sync(0xffffffffu, mx0, 2));
            mx1 = fmaxf(mx1, __shfl_xor_sync(0xffffffffu, mx1, 1));
            mx1 = fmaxf(mx1, __shfl_xor_sync(0xffffffffu, mx1, 2));

            const float m0n = fmaxf(m0, mx0);
            const float m1n = fmaxf(m1, mx1);
            const float corr0 = __expf(m0 - m0n);
            const float corr1 = __expf(m1 - m1n);

            float sum0 = 0.0f, sum1 = 0.0f;
            #pragma unroll
            for (int nt = 0; nt < 8; nt++) {
                s[nt][0] = __expf(s[nt][0] - m0n); sum0 += s[nt][0];
                s[nt][1] = __expf(s[nt][1] - m0n); sum0 += s[nt][1];
                s[nt][2] = __expf(s[nt][2] - m1n); sum1 += s[nt][2];
                s[nt][3] = __expf(s[nt][3] - m1n); sum1 += s[nt][3];
            }
            sum0 += __shfl_xor_sync(0xffffffffu, sum0, 1);
            sum0 += __shfl_xor_sync(0xffffffffu, sum0, 2);
            sum1 += __shfl_xor_sync(0xffffffffu, sum1, 1);
            sum1 += __shfl_xor_sync(0xffffffffu, sum1, 2);
            l0 = l0 * corr0 + sum0;
            l1 = l1 * corr1 + sum1;
            m0 = m0n; m1 = m1n;

            #pragma unroll
            for (int nt = 0; nt < 8; nt++) {
                o[nt][0] *= corr0; o[nt][1] *= corr0;
                o[nt][2] *= corr1; o[nt][3] *= corr1;
            }

            // ---- O += P V, 3-pass bf16. A-frags from S in-lane (no shuffles);
            //      B-frags = V^T via ldmatrix.x4.trans (serves nt=2p, 2p+1). ----
            #pragma unroll
            for (int ks = 0; ks < 4; ks++) {
                uint32_t ph[4], pl[4];
                bsplit2(s[2 * ks][0],     s[2 * ks][1],     ph[0], pl[0]);
                bsplit2(s[2 * ks][2],     s[2 * ks][3],     ph[1], pl[1]);
                bsplit2(s[2 * ks + 1][0], s[2 * ks + 1][1], ph[2], pl[2]);
                bsplit2(s[2 * ks + 1][2], s[2 * ks + 1][3], ph[3], pl[3]);

                const uint32_t koff = (uint32_t)(16 * ks * FP_STR) * 4u;
                #pragma unroll
                for (int p = 0; p < 4; p++) {
                    const uint32_t off = koff + (uint32_t)(8 * p) * 4u;
                    uint32_t vh[4], vl[4];
                    ldsm4t(vh, vhi_base + off);
                    ldsm4t(vl, vlo_base + off);
                    mma16(o[2 * p],     ph, vl);
                    mma16(o[2 * p],     pl, vh);
                    mma16(o[2 * p],     ph, vh);
                    mma16(o[2 * p + 1], ph, vl + 2);
                    mma16(o[2 * p + 1], pl, vh + 2);
                    mma16(o[2 * p + 1], ph, vh + 2);
                }
            }
        }
        __syncthreads();
    }

    // ---- normalize and store ----
    const float inv0 = 1.0f / l0;
    const float inv1 = 1.0f / l1;
    #pragma unroll
    for (int nt = 0; nt < 8; nt++) {
        const int col = h * HDIM + nt * 8 + 2 * tq;
        *(float2*)(g_A + (tok + r0) * DM + col) = make_float2(o[nt][0] * inv0, o[nt][1] * inv0);
        *(float2*)(g_A + (tok + r1) * DM + col) = make_float2(o[nt][2] * inv1, o[nt][3] * inv1);
    }
}

// ---------------------------------------------------------------------------
extern "C" void kernel_launch(void* const* d_in, const int* in_sizes, int n_in,
                              void* d_out, int out_size)
{
    (void)in_sizes; (void)n_in; (void)out_size;
    const float* x  = (const float*)d_in[0];
    const float* Wq = (const float*)d_in[1];
    const float* Wk = (const float*)d_in[2];
    const float* Wv = (const float*)d_in[3];
    const float* Wo = (const float*)d_in[4];
    const int*   tp = (const int*)d_in[6];
    float* out = (float*)d_out;

    dim3 ggrid(DM / 128, MTOK / 128);   // (8, 32)
    gemm_bf16_kernel<true,  0, 0><<<ggrid, 128>>>(x, Wq, nullptr, tp);
    gemm_bf16_kernel<true,  0, 1><<<ggrid, 128>>>(x, Wk, nullptr, tp);
    gemm_bf16_kernel<false, 0, 2><<<ggrid, 128>>>(x, Wv, nullptr, tp);

    dim3 fgrid(SEQ / 128, 2 * NHEAD);   // (16, 32)
    flash_attn_mma_kernel<<<fgrid, 256>>>();

    gemm_bf16_kernel<false, 1, 3><<<ggrid, 128>>>(nullptr, Wo, out, tp);
}